// round 12
// baseline (speedup 1.0000x reference)
#include <cuda_runtime.h>
#include <math.h>

#define HP   270
#define NPIX 72900
#define NB   2
#define ND   8
#define HIN  256

typedef unsigned long long u64;
typedef unsigned int u32;

__device__ float  g_xp[NB*NPIX];
__device__ float2 g_X [NB*NPIX];
__device__ float2 g_T1[ND*NPIX];
__device__ float2 g_Hf[NPIX];
__device__ float  g_S [NPIX];
__device__ float2 g_tw[HP];
__device__ float2 g_tempB[HP*15];
__device__ float2 g_tempG[24*HP*5];
__device__ float  g_ah[HP];
__device__ float  g_aw[HP];
__device__ float  g_z [ND*NPIX];
__device__ float  g_ww[24*25];
__device__ float  g_cw[32*25];
__device__ float  g_w1[5*64*32*9];
__device__ float  g_w2[5*32*64*9];
__device__ __align__(16) float g_w1t[5*4*9*64*12];
__device__ __align__(16) float g_w2t[5*8*9*32*12];
__device__ float  g_f0[ND*32*NPIX];
__device__ float  g_f1[ND*64*NPIX];
__device__ float  g_ct[ND*NPIX];
__device__ float  g_amp[4];
__device__ float  g_cstdn[ND];
__device__ float  g_nrm2[ND];
__device__ float  g_scl[ND];

static __device__ __forceinline__ int refl(int i, int n){
    if (i < 0)  i = -i - 1;
    if (i >= n) i = 2*n - 1 - i;
    return i;
}

static __device__ __forceinline__ u64 pack2(float lo, float hi){
    u64 r;
    asm("mov.b64 %0, {%1, %2};" : "=l"(r) : "f"(lo), "f"(hi));
    return r;
}
static __device__ __forceinline__ u64 ffma2(u64 a, u64 b, u64 c){
    u64 d;
    asm("fma.rn.f32x2 %0, %1, %2, %3;" : "=l"(d) : "l"(a), "l"(b), "l"(c));
    return d;
}
static __device__ __forceinline__ float2 unpack2(u64 v){
    float lo, hi;
    asm("mov.b64 {%0, %1}, %2;" : "=f"(lo), "=f"(hi) : "l"(v));
    return make_float2(lo, hi);
}
static __device__ __forceinline__ float f2tf32(float v){
    u32 u;
    asm("cvt.rna.tf32.f32 %0, %1;" : "=r"(u) : "f"(v));
    return __uint_as_float(u);
}
static __device__ __forceinline__ void mma_tf32(float* d, const u32* a, u32 b0, u32 b1){
    asm volatile(
        "mma.sync.aligned.m16n8k8.row.col.f32.tf32.tf32.f32 "
        "{%0,%1,%2,%3}, {%4,%5,%6,%7}, {%8,%9}, {%0,%1,%2,%3};"
        : "+f"(d[0]), "+f"(d[1]), "+f"(d[2]), "+f"(d[3])
        : "r"(a[0]), "r"(a[1]), "r"(a[2]), "r"(a[3]), "r"(b0), "r"(b1));
}

__global__ void k_init_tw(){
    int t = threadIdx.x;
    if (t < HP){
        double ang = -2.0 * 3.14159265358979323846 * (double)t / (double)HP;
        double s, c; sincos(ang, &s, &c);
        g_tw[t] = make_float2((float)c, (float)s);
    }
}

__global__ void k_pad(const float* __restrict__ x){
    int p = blockIdx.x*256 + threadIdx.x;
    if (p >= NPIX) return;
    int b = blockIdx.y;
    int y = p / HP, xx = p - y*HP;
    g_xp[b*NPIX + p] = x[b*HIN*HIN + refl(y-7,HIN)*HIN + refl(xx-7,HIN)];
}

__global__ void k_alphas(const float* __restrict__ bk){
    __shared__ float ph[15], pw[15], rh[15], rw[15];
    int t = threadIdx.x;
    if (t < 15){
        float s = 0.f, q = 0.f;
        for (int j = 0; j < 15; ++j){ s += bk[t*15+j]; q += bk[j*15+t]; }
        ph[t] = s; pw[t] = q;
    }
    __syncthreads();
    if (t < 15){
        float s = 0.f, q = 0.f;
        for (int j = 0; j + t < 15; ++j){ s += ph[j]*ph[j+t]; q += pw[j]*pw[j+t]; }
        rh[t] = s; rw[t] = q;
    }
    __syncthreads();
    if (t < HP){
        float zh = 0.f, zw = 0.f;
        if (t <= 14)       { zh = rh[t];       zw = rw[t];       }
        else if (t >= 255) { zh = rh[269 - t]; zw = rw[269 - t]; }
        g_ah[t] = 1.f - zh / rh[0];
        g_aw[t] = 1.f - zw / rw[0];
    }
}

__global__ void k_psf1(const float* __restrict__ bk){
    int tid = blockIdx.x*256 + threadIdx.x;
    if (tid >= HP*15) return;
    int u = tid / 15, w = tid - u*15;
    float ax = 0.f, ay = 0.f;
    for (int h = 0; h < 15; ++h){
        int rr = (h >= 7) ? (h - 7) : (h + 263);
        float2 t = g_tw[(u*rr) % HP];
        float v = bk[h*15 + w];
        ax += v*t.x; ay += v*t.y;
    }
    g_tempB[tid] = make_float2(ax, ay);
}

__global__ void k_psf2(){
    int p = blockIdx.x*256 + threadIdx.x;
    if (p >= NPIX) return;
    int u = p / HP, v = p - u*HP;
    float ax = 0.f, ay = 0.f;
    for (int w = 0; w < 15; ++w){
        int rr = (w >= 7) ? (w - 7) : (w + 263);
        float2 t = g_tw[(v*rr) % HP];
        float2 b = g_tempB[u*15 + w];
        ax += b.x*t.x - b.y*t.y;
        ay += b.x*t.y + b.y*t.x;
    }
    g_Hf[p] = make_float2(ax, ay);
}

__global__ void k_wnorm(const float* __restrict__ w, const float* __restrict__ sc,
                        float* __restrict__ out, int sz){
    int ch = blockIdx.x;
    const float* src = w + (size_t)ch*sz;
    int lane = threadIdx.x;
    float s = 0.f;
    for (int i = lane; i < sz; i += 32) s += src[i];
    #pragma unroll
    for (int o = 16; o; o >>= 1) s += __shfl_xor_sync(0xffffffffu, s, o);
    float mean = s / (float)sz;
    float q = 0.f;
    for (int i = lane; i < sz; i += 32){ float v = src[i]-mean; q += v*v; }
    #pragma unroll
    for (int o = 16; o; o >>= 1) q += __shfl_xor_sync(0xffffffffu, q, o);
    float inv = sc[ch] / sqrtf(q);
    for (int i = lane; i < sz; i += 32) out[(size_t)ch*sz + i] = (src[i]-mean)*inv;
}

template<int CIN, int COUT>
__global__ void k_wprep(const float* __restrict__ wn, float* __restrict__ dst){
    int layer = blockIdx.y;
    const float* w = wn + (size_t)layer*COUT*CIN*9;
    float* d = dst + (size_t)layer*(CIN/8)*9*COUT*12;
    int total = (CIN/8)*9*COUT*8;
    for (int i = blockIdx.x*256 + threadIdx.x; i < total; i += gridDim.x*256){
        int ck  = i / (9*COUT*8);
        int r   = i - ck*9*COUT*8;
        int tap = r / (COUT*8);
        int r2  = r - tap*(COUT*8);
        int oc  = r2 >> 3, ci = r2 & 7;
        d[(((size_t)ck*9 + tap)*COUT + oc)*12 + ci] =
            f2tf32(w[((size_t)oc*CIN + ck*8 + ci)*9 + tap]);
    }
}

__global__ void k_wien1(){
    int tid = blockIdx.x*256 + threadIdx.x;
    if (tid >= 24*HP*5) return;
    int o = tid / (HP*5);
    int r = tid - o*HP*5;
    int u = r / 5, w = r - u*5;
    float ax = 0.f, ay = 0.f;
    for (int h = 0; h < 5; ++h){
        int rr = (h >= 2) ? (h - 2) : (h + 268);
        float2 t = g_tw[(u*rr) % HP];
        float v = g_ww[o*25 + h*5 + w];
        ax += v*t.x; ay += v*t.y;
    }
    g_tempG[tid] = make_float2(ax, ay);
}

__global__ void k_S(){
    int p = blockIdx.x*256 + threadIdx.x;
    if (p >= NPIX) return;
    int u = p / HP, v = p - u*HP;
    float2 tws[5];
    #pragma unroll
    for (int w = 0; w < 5; ++w){
        int rr = (w >= 2) ? (w - 2) : (w + 268);
        tws[w] = g_tw[(v*rr) % HP];
    }
    float s = 0.f;
    for (int o = 0; o < 24; ++o){
        float ax = 0.f, ay = 0.f;
        int base = (o*HP + u)*5;
        #pragma unroll
        for (int w = 0; w < 5; ++w){
            float2 g = g_tempG[base + w];
            float2 t = tws[w];
            ax += g.x*t.x - g.y*t.y;
            ay += g.x*t.y + g.y*t.x;
        }
        s += ax*ax + ay*ay;
    }
    g_S[p] = s;
}

// ===== Cooley-Tukey 270 = 27x10 DFT line kernels ======================

__global__ void k_dft_rows_real(const float* __restrict__ in, float2* __restrict__ out){
    __shared__ float sv[HP];
    __shared__ __align__(8) u64 sTA[HP], sTB[HP], sT10[10], sG[HP];
    int plane = blockIdx.y, row = blockIdx.x;
    const float* src = in + (size_t)plane*NPIX + (size_t)row*HP;
    for (int i = threadIdx.x; i < HP; i += blockDim.x){
        sv[i] = src[i];
        float2 t = g_tw[i];
        sTA[i] = pack2(t.x, t.x);
        sTB[i] = pack2(t.y, t.y);
    }
    if (threadIdx.x < 10){
        float2 t = g_tw[27*threadIdx.x];
        sT10[threadIdx.x] = pack2(t.x, t.y);
    }
    __syncthreads();
    int t = threadIdx.x;
    if (t < HP){
        int n2 = t % 27, k1 = t / 27;
        u64 acc = 0; int idx = 0;
        #pragma unroll
        for (int n1 = 0; n1 < 10; ++n1){
            float s = sv[27*n1 + n2];
            acc = ffma2(pack2(s, s), sT10[idx], acc);
            idx += k1; if (idx >= 10) idx -= 10;
        }
        sG[t] = acc;
    }
    __syncthreads();
    if (t < HP){
        int k1 = t % 10;
        u64 P = 0, Q = 0; int idx = 0;
        #pragma unroll 3
        for (int n2 = 0; n2 < 27; ++n2){
            u64 g = sG[k1*27 + n2];
            P = ffma2(g, sTA[idx], P);
            Q = ffma2(g, sTB[idx], Q);
            idx += t; if (idx >= HP) idx -= HP;
        }
        float2 p = unpack2(P), q = unpack2(Q);
        out[(size_t)plane*NPIX + (size_t)row*HP + t] = make_float2(p.x - q.y, p.y + q.x);
    }
}

// MODE 0: plain; MODE 1: rows ×Hf; MODE 2: rows, full Wiener T product
template<int ROWS, int MODE>
__global__ void k_dft_line_c(const float2* __restrict__ in, float2* __restrict__ out,
                             float sgn, float scale, const float* __restrict__ alpha){
    __shared__ __align__(8) u64 sv[HP];
    __shared__ __align__(8) u64 sTA[HP], sTB[HP], sG[HP];
    int plane = blockIdx.y, line = blockIdx.x;
    int srcplane = (MODE == 2) ? (plane >> 2) : plane;
    const float2* src = in + (size_t)srcplane*NPIX + (ROWS ? (size_t)line*HP : (size_t)line);
    float ad = 0.f;
    if (MODE == 2) ad = expf(alpha[plane & 3]);
    for (int i = threadIdx.x; i < HP; i += blockDim.x){
        float2 v = ROWS ? src[i] : src[(size_t)i*HP];
        if (MODE == 1){
            float2 H = g_Hf[line*HP + i];
            v = make_float2(v.x*H.x - v.y*H.y, v.x*H.y + v.y*H.x);
        } else if (MODE == 2){
            int p = line*HP + i;
            float2 H = g_Hf[p];
            float den = H.x*H.x + H.y*H.y + ad*g_S[p];
            float Tx =  H.x/den, Ty = -H.y/den;
            v = make_float2(Tx*v.x - Ty*v.y, Tx*v.y + Ty*v.x);
        }
        sv[i] = pack2(v.x, v.y);
        float2 t = g_tw[i];
        float ty = sgn*t.y;
        sTA[i] = pack2(t.x, t.x);
        sTB[i] = pack2(ty, ty);
    }
    __syncthreads();
    int t = threadIdx.x;
    if (t < HP){
        int n2 = t % 27, k1 = t / 27;
        u64 PA = 0, QA = 0; int idx = 0;
        #pragma unroll
        for (int n1 = 0; n1 < 10; ++n1){
            u64 s = sv[27*n1 + n2];
            PA = ffma2(s, sTA[27*idx], PA);
            QA = ffma2(s, sTB[27*idx], QA);
            idx += k1; if (idx >= 10) idx -= 10;
        }
        float2 p = unpack2(PA), q = unpack2(QA);
        sG[t] = pack2(p.x - q.y, p.y + q.x);
    }
    __syncthreads();
    if (t < HP){
        int k1 = t % 10;
        u64 P = 0, Q = 0; int idx = 0;
        #pragma unroll 3
        for (int n2 = 0; n2 < 27; ++n2){
            u64 g = sG[k1*27 + n2];
            P = ffma2(g, sTA[idx], P);
            Q = ffma2(g, sTB[idx], Q);
            idx += t; if (idx >= HP) idx -= HP;
        }
        float2 p = unpack2(P), q = unpack2(Q);
        size_t o = (size_t)plane*NPIX + (ROWS ? ((size_t)line*HP + t) : ((size_t)t*HP + line));
        out[o] = make_float2((p.x - q.y)*scale, (p.y + q.x)*scale);
    }
}

// MODE 0: write out; MODE 1: edgetaper blend into g_xp (out unused)
template<int MODE>
__global__ void k_dft_cols_real(const float2* __restrict__ in, float* __restrict__ out,
                                float sgn, float scale){
    __shared__ __align__(8) u64 sv[HP];
    __shared__ __align__(8) u64 sTA[HP], sTB[HP], sTC[HP], sG[HP];
    int plane = blockIdx.y, col = blockIdx.x;
    const float2* src = in + (size_t)plane*NPIX + col;
    for (int i = threadIdx.x; i < HP; i += blockDim.x){
        float2 v = src[(size_t)i*HP];
        sv[i] = pack2(v.x, v.y);
        float2 t = g_tw[i];
        float ty = sgn*t.y;
        sTA[i] = pack2(t.x, t.x);
        sTB[i] = pack2(ty, ty);
        sTC[i] = pack2(t.x, -ty);
    }
    __syncthreads();
    int t = threadIdx.x;
    if (t < HP){
        int n2 = t % 27, k1 = t / 27;
        u64 PA = 0, QA = 0; int idx = 0;
        #pragma unroll
        for (int n1 = 0; n1 < 10; ++n1){
            u64 s = sv[27*n1 + n2];
            PA = ffma2(s, sTA[27*idx], PA);
            QA = ffma2(s, sTB[27*idx], QA);
            idx += k1; if (idx >= 10) idx -= 10;
        }
        float2 p = unpack2(PA), q = unpack2(QA);
        sG[t] = pack2(p.x - q.y, p.y + q.x);
    }
    __syncthreads();
    if (t < HP){
        int k1 = t % 10;
        u64 acc = 0; int idx = 0;
        #pragma unroll 3
        for (int n2 = 0; n2 < 27; ++n2){
            acc = ffma2(sG[k1*27 + n2], sTC[idx], acc);
            idx += t; if (idx >= HP) idx -= HP;
        }
        float2 a = unpack2(acc);
        float val = (a.x + a.y)*scale;
        size_t o = (size_t)plane*NPIX + (size_t)t*HP + col;
        if (MODE == 1){
            float aa = g_ah[t]*g_aw[col];
            g_xp[o] = aa*g_xp[o] + (1.f - aa)*val;
        } else {
            out[o] = val;
        }
    }
}

__global__ void k_amp(const float* __restrict__ alpha){
    __shared__ float red[256];
    int d = blockIdx.x;
    float ad = expf(alpha[d]);
    float s = 0.f;
    for (int p = threadIdx.x; p < NPIX; p += 256){
        float2 H = g_Hf[p];
        float h2 = H.x*H.x + H.y*H.y;
        float den = h2 + ad*g_S[p];
        s += h2 / (den*den);
    }
    red[threadIdx.x] = s; __syncthreads();
    for (int o = 128; o; o >>= 1){
        if (threadIdx.x < o) red[threadIdx.x] += red[threadIdx.x + o];
        __syncthreads();
    }
    if (threadIdx.x == 0) g_amp[d] = red[0] / (float)NPIX;
}

__global__ void k_cstdn(const float* __restrict__ stdn){
    int n = threadIdx.x;
    if (n < ND){
        int b = n >> 2, d = n & 3;
        g_cstdn[n] = sqrtf(stdn[b]*stdn[b]*g_amp[d]);
    }
}

__global__ __launch_bounds__(256) void k_conv1(const float* __restrict__ bias){
    __shared__ float s_in[20*20];
    __shared__ __align__(8) u64 s_wp[25*16];
    int n = blockIdx.z;
    int ty = threadIdx.y, tx = threadIdx.x;
    int tid = ty*16 + tx;
    int y0 = blockIdx.y*16 - 2, x0 = blockIdx.x*16 - 2;
    const float* src = g_z + (size_t)n*NPIX;
    for (int i = tid; i < 400; i += 256){
        int r = i / 20, c = i - r*20;
        s_in[i] = src[refl(y0+r,HP)*HP + refl(x0+c,HP)];
    }
    for (int i = tid; i < 400; i += 256){
        int tap = i >> 4, op = i & 15;
        s_wp[i] = pack2(g_cw[(2*op)*25 + tap], g_cw[(2*op+1)*25 + tap]);
    }
    __syncthreads();
    u64 acc[16];
    #pragma unroll
    for (int op = 0; op < 16; ++op) acc[op] = pack2(bias[2*op], bias[2*op+1]);
    #pragma unroll
    for (int ky = 0; ky < 5; ++ky)
        #pragma unroll
        for (int kx = 0; kx < 5; ++kx){
            float v = s_in[(ty+ky)*20 + tx + kx];
            u64 vv = pack2(v, v);
            int tap = ky*5 + kx;
            #pragma unroll
            for (int op = 0; op < 16; ++op)
                acc[op] = ffma2(vv, s_wp[tap*16 + op], acc[op]);
        }
    int oy = blockIdx.y*16 + ty, ox = blockIdx.x*16 + tx;
    if (oy < HP && ox < HP){
        #pragma unroll
        for (int op = 0; op < 16; ++op){
            float2 v = unpack2(acc[op]);
            g_f0[((size_t)n*32 + 2*op  )*NPIX + oy*HP + ox] = v.x;
            g_f0[((size_t)n*32 + 2*op+1)*NPIX + oy*HP + ox] = v.y;
        }
    }
}

// ---- tf32 mma conv, 16x32 px tile, nt=8 per warp ------------------------
#define SINS 616   // 18*34=612 padded so stride%32==8
template<int CIN, int COUT>
__global__ __launch_bounds__(256,1) void k_mma_conv(
    const float* __restrict__ in, const float* __restrict__ wt,
    const float* __restrict__ bias, const float* __restrict__ prelu,
    const float* __restrict__ skip, float* __restrict__ out)
{
    constexpr int MT  = COUT/16;
    constexpr int NCH = CIN/8;
    __shared__ __align__(16) float s_in[8*SINS];
    __shared__ __align__(16) float w_s[9*COUT*12];

    int n  = blockIdx.z;
    int y0 = blockIdx.y*16, x0 = blockIdx.x*32;
    int tid  = threadIdx.x;
    int lane = tid & 31, wp = tid >> 5;
    int gid  = lane >> 2, tig = lane & 3;

    bool interior = (y0 >= 1) && (y0 <= HP-17) && (x0 >= 1) && (x0 <= HP-33);

    float d[MT][8][4];
    #pragma unroll
    for (int m = 0; m < MT; ++m){
        float blo = bias[m*16 + gid];
        float bhi = bias[m*16 + gid + 8];
        #pragma unroll
        for (int nt = 0; nt < 8; ++nt){
            d[m][nt][0] = blo; d[m][nt][1] = blo;
            d[m][nt][2] = bhi; d[m][nt][3] = bhi;
        }
    }

    const float* inb = in + (size_t)n*CIN*NPIX;
    for (int ck = 0; ck < NCH; ++ck){
        __syncthreads();
        {
            const float4* ws4 = (const float4*)(wt + (size_t)ck*9*COUT*12);
            float4* wd4 = (float4*)w_s;
            for (int i = tid; i < 9*COUT*3; i += 256) wd4[i] = ws4[i];
        }
        {
            int cin = ck*8 + wp;
            const float* src = inb + (size_t)cin*NPIX;
            float sl = prelu[cin];
            float* dst = &s_in[wp*SINS];
            if (interior){
                const float* p0 = src + (size_t)(y0-1)*HP + (x0-1);
                for (int j = lane; j < 612; j += 32){
                    int yy = j / 34, xx = j - yy*34;
                    float v = p0[yy*HP + xx];
                    dst[j] = f2tf32((v >= 0.f) ? v : v*sl);
                }
            } else {
                for (int j = lane; j < 612; j += 32){
                    int yy = j / 34, xx = j - yy*34;
                    float v = src[refl(y0-1+yy,HP)*HP + refl(x0-1+xx,HP)];
                    dst[j] = f2tf32((v >= 0.f) ? v : v*sl);
                }
            }
        }
        __syncthreads();

        #pragma unroll
        for (int tap = 0; tap < 9; ++tap){
            int ky = tap/3, kx = tap - 3*(tap/3);
            u32 a[MT][4];
            #pragma unroll
            for (int m = 0; m < MT; ++m){
                int base = (tap*COUT + m*16 + gid)*12 + tig;
                a[m][0] = __float_as_uint(w_s[base]);
                a[m][1] = __float_as_uint(w_s[base + 8*12]);
                a[m][2] = __float_as_uint(w_s[base + 4]);
                a[m][3] = __float_as_uint(w_s[base + 8*12 + 4]);
            }
            #pragma unroll
            for (int nt = 0; nt < 8; ++nt){
                int r  = nt >> 2, c8 = nt & 3;
                int yy  = 2*wp + r + ky;
                int xxb = c8*8 + gid + kx;
                u32 b0 = __float_as_uint(s_in[tig*SINS + yy*34 + xxb]);
                u32 b1 = __float_as_uint(s_in[(tig+4)*SINS + yy*34 + xxb]);
                #pragma unroll
                for (int m = 0; m < MT; ++m)
                    mma_tf32(d[m][nt], a[m], b0, b1);
            }
        }
    }

    #pragma unroll
    for (int m = 0; m < MT; ++m){
        #pragma unroll
        for (int nt = 0; nt < 8; ++nt){
            int r  = nt >> 2, c8 = nt & 3;
            int y = y0 + 2*wp + r;
            int x = x0 + c8*8 + 2*tig;
            if (y < HP && x < HP){
                int oc = m*16 + gid;
                size_t p0 = ((size_t)n*COUT + oc)*NPIX + (size_t)y*HP + x;
                size_t p1 = p0 + (size_t)8*NPIX;
                float2 v0 = make_float2(d[m][nt][0], d[m][nt][1]);
                float2 v1 = make_float2(d[m][nt][2], d[m][nt][3]);
                if (skip){
                    float2 s0 = *(const float2*)(skip + p0);
                    float2 s1 = *(const float2*)(skip + p1);
                    v0.x += s0.x; v0.y += s0.y;
                    v1.x += s1.x; v1.y += s1.y;
                }
                *(float2*)(out + p0) = v0;
                *(float2*)(out + p1) = v1;
            }
        }
    }
}

__global__ __launch_bounds__(256) void k_convT(const float* __restrict__ in,
                                               const float* __restrict__ biasT){
    __shared__ __align__(8) u64 s_in2[20*20];
    __shared__ __align__(8) u64 s_wp[25];
    int n = blockIdx.z;
    int ty = threadIdx.y, tx = threadIdx.x;
    int tid = ty*16 + tx;
    int y0 = blockIdx.y*16, x0 = blockIdx.x*16;
    u64 acc2 = 0;
    for (int op = 0; op < 16; ++op){
        __syncthreads();
        const float* src0 = in + ((size_t)n*32 + 2*op)*NPIX;
        const float* src1 = src0 + NPIX;
        for (int i = tid; i < 400; i += 256){
            int r = i / 20, c = i - r*20;
            int yy = y0 - 2 + r, xx = x0 - 2 + c;
            if (yy >= 0 && yy < HP && xx >= 0 && xx < HP){
                size_t o = (size_t)yy*HP + xx;
                s_in2[i] = pack2(src0[o], src1[o]);
            } else s_in2[i] = 0;
        }
        if (tid < 25) s_wp[tid] = pack2(g_cw[(2*op)*25 + tid], g_cw[(2*op+1)*25 + tid]);
        __syncthreads();
        #pragma unroll
        for (int u = 0; u < 5; ++u)
            #pragma unroll
            for (int v = 0; v < 5; ++v)
                acc2 = ffma2(s_in2[(ty + 4 - u)*20 + tx + 4 - v], s_wp[u*5 + v], acc2);
    }
    int oy = y0 + ty, ox = x0 + tx;
    if (oy < HP && ox < HP){
        float2 a = unpack2(acc2);
        g_ct[(size_t)n*NPIX + oy*HP + ox] = biasT[0] + a.x + a.y;
    }
}

__global__ void k_nrm(){
    __shared__ float red[256];
    int n = blockIdx.x;
    float s = 0.f;
    for (int p = threadIdx.x; p < NPIX; p += 256){
        float v = g_ct[(size_t)n*NPIX + p];
        s += v*v;
    }
    red[threadIdx.x] = s; __syncthreads();
    for (int o = 128; o; o >>= 1){
        if (threadIdx.x < o) red[threadIdx.x] += red[threadIdx.x + o];
        __syncthreads();
    }
    if (threadIdx.x == 0) g_nrm2[n] = red[0];
}

__global__ void k_scl(const float* __restrict__ ap){
    int n = threadIdx.x;
    if (n < ND){
        float eps = expf(ap[0]) * g_cstdn[n] * sqrtf((float)(NPIX - 1));
        float nr  = sqrtf(g_nrm2[n]);
        g_scl[n] = (nr > eps) ? eps / fmaxf(nr, 1e-12f) : 1.f;
    }
}

__global__ void k_final(const float* __restrict__ mw, float* __restrict__ outp){
    int b = blockIdx.y;
    int p = blockIdx.x*256 + threadIdx.x;
    int y = p >> 8, x = p & 255;
    size_t q = (size_t)(y + 7)*HP + (x + 7);
    float acc = 0.f;
    #pragma unroll
    for (int d = 0; d < 4; ++d){
        int n = b*4 + d;
        float r = g_z[(size_t)n*NPIX + q] - g_ct[(size_t)n*NPIX + q]*g_scl[n];
        r = fminf(fmaxf(r, 0.f), 255.f);
        acc += mw[d]*r;
    }
    outp[(size_t)b*65536 + p] = acc;
}

extern "C" void kernel_launch(void* const* d_in, const int* in_sizes, int n_in,
                              void* d_out, int out_size){
    const float* x      = (const float*)d_in[0];
    const float* bk     = (const float*)d_in[1];
    const float* stdn   = (const float*)d_in[2];
    const float* wienw  = (const float*)d_in[3];
    const float* wiensc = (const float*)d_in[4];
    const float* alpha  = (const float*)d_in[5];
    const float* convw  = (const float*)d_in[6];
    const float* scalef = (const float*)d_in[7];
    const float* biasf  = (const float*)d_in[8];
    const float* biast  = (const float*)d_in[9];
    const float* p1     = (const float*)d_in[10];
    const float* w1     = (const float*)d_in[11];
    const float* s1     = (const float*)d_in[12];
    const float* b1     = (const float*)d_in[13];
    const float* p2     = (const float*)d_in[14];
    const float* w2     = (const float*)d_in[15];
    const float* s2     = (const float*)d_in[16];
    const float* b2     = (const float*)d_in[17];
    const float* aproj  = (const float*)d_in[18];
    const float* mw     = (const float*)d_in[19];
    float* outp = (float*)d_out;

    float *pxp, *pz, *pww, *pcw, *pw1, *pw2, *pw1t, *pw2t, *pf0, *pf1;
    float2 *pX, *pT1;
    cudaGetSymbolAddress((void**)&pxp, g_xp);
    cudaGetSymbolAddress((void**)&pz,  g_z);
    cudaGetSymbolAddress((void**)&pww, g_ww);
    cudaGetSymbolAddress((void**)&pcw, g_cw);
    cudaGetSymbolAddress((void**)&pw1, g_w1);
    cudaGetSymbolAddress((void**)&pw2, g_w2);
    cudaGetSymbolAddress((void**)&pw1t, g_w1t);
    cudaGetSymbolAddress((void**)&pw2t, g_w2t);
    cudaGetSymbolAddress((void**)&pf0, g_f0);
    cudaGetSymbolAddress((void**)&pf1, g_f1);
    cudaGetSymbolAddress((void**)&pX,  g_X);
    cudaGetSymbolAddress((void**)&pT1, g_T1);

    const int PB = (NPIX + 255)/256;
    const float INV = 1.0f/(float)HP;

    k_init_tw<<<1, 288>>>();
    k_wnorm<<<24, 32>>>(wienw, wiensc, pww, 25);
    k_wnorm<<<32, 32>>>(convw, scalef, pcw, 25);
    k_wnorm<<<320, 32>>>(w1, s1, pw1, 288);
    k_wnorm<<<160, 32>>>(w2, s2, pw2, 576);
    k_wprep<32,64><<<dim3(72,5), 256>>>(pw1, pw1t);
    k_wprep<64,32><<<dim3(72,5), 256>>>(pw2, pw2t);

    k_pad<<<dim3(PB, NB), 256>>>(x);
    k_alphas<<<1, 288>>>(bk);
    k_psf1<<<(HP*15 + 255)/256, 256>>>(bk);
    k_psf2<<<PB, 256>>>();
    k_wien1<<<(24*HP*5 + 255)/256, 256>>>();
    k_S<<<PB, 256>>>();

    // fft2(xp) -> X
    k_dft_rows_real<<<dim3(HP, NB), 288>>>(pxp, pT1);
    k_dft_line_c<0,0><<<dim3(HP, NB), 288>>>(pT1, pX, 1.f, 1.f, nullptr);
    // edgetaper: ifft2(X*Hf).real blended into xp (fused)
    k_dft_line_c<1,1><<<dim3(HP, NB), 288>>>(pX, pT1, -1.f, INV, nullptr);
    k_dft_cols_real<1><<<dim3(HP, NB), 288>>>(pT1, nullptr, -1.f, INV);

    // Y = fft2(xp) -> X
    k_dft_rows_real<<<dim3(HP, NB), 288>>>(pxp, pT1);
    k_dft_line_c<0,0><<<dim3(HP, NB), 288>>>(pT1, pX, 1.f, 1.f, nullptr);

    k_amp<<<4, 256>>>(alpha);
    k_cstdn<<<1, 32>>>(stdn);

    // z = ifft2(T * Y).real (Wiener product fused)
    k_dft_line_c<1,2><<<dim3(HP, ND), 288>>>(pX, pT1, -1.f, INV, alpha);
    k_dft_cols_real<0><<<dim3(HP, ND), 288>>>(pT1, pz, -1.f, INV);

    // CNN
    k_conv1<<<dim3(17,17,ND), dim3(16,16)>>>(biasf);
    for (int i = 0; i < 5; ++i){
        k_mma_conv<32,64><<<dim3(9,17,ND), 256>>>(
            pf0, pw1t + (size_t)i*4*9*64*12, b1 + i*64, p1 + i*32, nullptr, pf1);
        k_mma_conv<64,32><<<dim3(9,17,ND), 256>>>(
            pf1, pw2t + (size_t)i*8*9*32*12, b2 + i*32, p2 + i*64,
            (i == 0) ? pf0 : nullptr, pf0);
    }
    k_convT<<<dim3(17,17,ND), dim3(16,16)>>>(pf0, biast);

    k_nrm<<<ND, 256>>>();
    k_scl<<<1, 32>>>(aproj);
    k_final<<<dim3(256, NB), 256>>>(mw, outp);
}

// round 13
// speedup vs baseline: 1.6823x; 1.6823x over previous
#include <cuda_runtime.h>
#include <math.h>

#define HP   270
#define NPIX 72900
#define NB   2
#define ND   8
#define HIN  256

typedef unsigned long long u64;
typedef unsigned int u32;

__device__ float  g_xp[NB*NPIX];
__device__ float2 g_X [NB*NPIX];
__device__ float2 g_T1[ND*NPIX];
__device__ float2 g_Hf[NPIX];
__device__ float  g_S [NPIX];
__device__ float2 g_tw[HP];
__device__ float2 g_tempB[HP*15];
__device__ float2 g_tempG[24*HP*5];
__device__ float  g_ah[HP];
__device__ float  g_aw[HP];
__device__ float  g_z [ND*NPIX];
__device__ float  g_ww[24*25];
__device__ float  g_cw[32*25];
__device__ float  g_w1[5*64*32*9];
__device__ float  g_w2[5*32*64*9];
__device__ __align__(16) float g_w1t[5*4*9*64*12];
__device__ __align__(16) float g_w2t[5*8*9*32*12];
__device__ float  g_f0[ND*32*NPIX];
__device__ float  g_f1[ND*64*NPIX];
__device__ float  g_ct[ND*NPIX];
__device__ float  g_amp[4];
__device__ float  g_cstdn[ND];
__device__ float  g_nrm2[ND];
__device__ float  g_scl[ND];

static __device__ __forceinline__ int refl(int i, int n){
    if (i < 0)  i = -i - 1;
    if (i >= n) i = 2*n - 1 - i;
    return i;
}

static __device__ __forceinline__ u64 pack2(float lo, float hi){
    u64 r;
    asm("mov.b64 %0, {%1, %2};" : "=l"(r) : "f"(lo), "f"(hi));
    return r;
}
static __device__ __forceinline__ u64 ffma2(u64 a, u64 b, u64 c){
    u64 d;
    asm("fma.rn.f32x2 %0, %1, %2, %3;" : "=l"(d) : "l"(a), "l"(b), "l"(c));
    return d;
}
static __device__ __forceinline__ float2 unpack2(u64 v){
    float lo, hi;
    asm("mov.b64 {%0, %1}, %2;" : "=f"(lo), "=f"(hi) : "l"(v));
    return make_float2(lo, hi);
}
static __device__ __forceinline__ float f2tf32(float v){
    u32 u;
    asm("cvt.rna.tf32.f32 %0, %1;" : "=r"(u) : "f"(v));
    return __uint_as_float(u);
}
static __device__ __forceinline__ void mma_tf32(float* d, const u32* a, u32 b0, u32 b1){
    asm volatile(
        "mma.sync.aligned.m16n8k8.row.col.f32.tf32.tf32.f32 "
        "{%0,%1,%2,%3}, {%4,%5,%6,%7}, {%8,%9}, {%0,%1,%2,%3};"
        : "+f"(d[0]), "+f"(d[1]), "+f"(d[2]), "+f"(d[3])
        : "r"(a[0]), "r"(a[1]), "r"(a[2]), "r"(a[3]), "r"(b0), "r"(b1));
}

__global__ void k_init_tw(){
    int t = threadIdx.x;
    if (t < HP){
        double ang = -2.0 * 3.14159265358979323846 * (double)t / (double)HP;
        double s, c; sincos(ang, &s, &c);
        g_tw[t] = make_float2((float)c, (float)s);
    }
}

__global__ void k_pad(const float* __restrict__ x){
    int p = blockIdx.x*256 + threadIdx.x;
    if (p >= NPIX) return;
    int b = blockIdx.y;
    int y = p / HP, xx = p - y*HP;
    g_xp[b*NPIX + p] = x[b*HIN*HIN + refl(y-7,HIN)*HIN + refl(xx-7,HIN)];
}

__global__ void k_alphas(const float* __restrict__ bk){
    __shared__ float ph[15], pw[15], rh[15], rw[15];
    int t = threadIdx.x;
    if (t < 15){
        float s = 0.f, q = 0.f;
        for (int j = 0; j < 15; ++j){ s += bk[t*15+j]; q += bk[j*15+t]; }
        ph[t] = s; pw[t] = q;
    }
    __syncthreads();
    if (t < 15){
        float s = 0.f, q = 0.f;
        for (int j = 0; j + t < 15; ++j){ s += ph[j]*ph[j+t]; q += pw[j]*pw[j+t]; }
        rh[t] = s; rw[t] = q;
    }
    __syncthreads();
    if (t < HP){
        float zh = 0.f, zw = 0.f;
        if (t <= 14)       { zh = rh[t];       zw = rw[t];       }
        else if (t >= 255) { zh = rh[269 - t]; zw = rw[269 - t]; }
        g_ah[t] = 1.f - zh / rh[0];
        g_aw[t] = 1.f - zw / rw[0];
    }
}

__global__ void k_psf1(const float* __restrict__ bk){
    int tid = blockIdx.x*256 + threadIdx.x;
    if (tid >= HP*15) return;
    int u = tid / 15, w = tid - u*15;
    float ax = 0.f, ay = 0.f;
    for (int h = 0; h < 15; ++h){
        int rr = (h >= 7) ? (h - 7) : (h + 263);
        float2 t = g_tw[(u*rr) % HP];
        float v = bk[h*15 + w];
        ax += v*t.x; ay += v*t.y;
    }
    g_tempB[tid] = make_float2(ax, ay);
}

__global__ void k_psf2(){
    int p = blockIdx.x*256 + threadIdx.x;
    if (p >= NPIX) return;
    int u = p / HP, v = p - u*HP;
    float ax = 0.f, ay = 0.f;
    for (int w = 0; w < 15; ++w){
        int rr = (w >= 7) ? (w - 7) : (w + 263);
        float2 t = g_tw[(v*rr) % HP];
        float2 b = g_tempB[u*15 + w];
        ax += b.x*t.x - b.y*t.y;
        ay += b.x*t.y + b.y*t.x;
    }
    g_Hf[p] = make_float2(ax, ay);
}

__global__ void k_wnorm(const float* __restrict__ w, const float* __restrict__ sc,
                        float* __restrict__ out, int sz){
    int ch = blockIdx.x;
    const float* src = w + (size_t)ch*sz;
    int lane = threadIdx.x;
    float s = 0.f;
    for (int i = lane; i < sz; i += 32) s += src[i];
    #pragma unroll
    for (int o = 16; o; o >>= 1) s += __shfl_xor_sync(0xffffffffu, s, o);
    float mean = s / (float)sz;
    float q = 0.f;
    for (int i = lane; i < sz; i += 32){ float v = src[i]-mean; q += v*v; }
    #pragma unroll
    for (int o = 16; o; o >>= 1) q += __shfl_xor_sync(0xffffffffu, q, o);
    float inv = sc[ch] / sqrtf(q);
    for (int i = lane; i < sz; i += 32) out[(size_t)ch*sz + i] = (src[i]-mean)*inv;
}

template<int CIN, int COUT>
__global__ void k_wprep(const float* __restrict__ wn, float* __restrict__ dst){
    int layer = blockIdx.y;
    const float* w = wn + (size_t)layer*COUT*CIN*9;
    float* d = dst + (size_t)layer*(CIN/8)*9*COUT*12;
    int total = (CIN/8)*9*COUT*8;
    for (int i = blockIdx.x*256 + threadIdx.x; i < total; i += gridDim.x*256){
        int ck  = i / (9*COUT*8);
        int r   = i - ck*9*COUT*8;
        int tap = r / (COUT*8);
        int r2  = r - tap*(COUT*8);
        int oc  = r2 >> 3, ci = r2 & 7;
        d[(((size_t)ck*9 + tap)*COUT + oc)*12 + ci] =
            f2tf32(w[((size_t)oc*CIN + ck*8 + ci)*9 + tap]);
    }
}

__global__ void k_wien1(){
    int tid = blockIdx.x*256 + threadIdx.x;
    if (tid >= 24*HP*5) return;
    int o = tid / (HP*5);
    int r = tid - o*HP*5;
    int u = r / 5, w = r - u*5;
    float ax = 0.f, ay = 0.f;
    for (int h = 0; h < 5; ++h){
        int rr = (h >= 2) ? (h - 2) : (h + 268);
        float2 t = g_tw[(u*rr) % HP];
        float v = g_ww[o*25 + h*5 + w];
        ax += v*t.x; ay += v*t.y;
    }
    g_tempG[tid] = make_float2(ax, ay);
}

__global__ void k_S(){
    int p = blockIdx.x*256 + threadIdx.x;
    if (p >= NPIX) return;
    int u = p / HP, v = p - u*HP;
    float2 tws[5];
    #pragma unroll
    for (int w = 0; w < 5; ++w){
        int rr = (w >= 2) ? (w - 2) : (w + 268);
        tws[w] = g_tw[(v*rr) % HP];
    }
    float s = 0.f;
    for (int o = 0; o < 24; ++o){
        float ax = 0.f, ay = 0.f;
        int base = (o*HP + u)*5;
        #pragma unroll
        for (int w = 0; w < 5; ++w){
            float2 g = g_tempG[base + w];
            float2 t = tws[w];
            ax += g.x*t.x - g.y*t.y;
            ay += g.x*t.y + g.y*t.x;
        }
        s += ax*ax + ay*ay;
    }
    g_S[p] = s;
}

// ===== Cooley-Tukey 270 = 27x10 DFT line kernels ======================

__global__ void k_dft_rows_real(const float* __restrict__ in, float2* __restrict__ out){
    __shared__ float sv[HP];
    __shared__ __align__(8) u64 sTA[HP], sTB[HP], sT10[10], sG[HP];
    int plane = blockIdx.y, row = blockIdx.x;
    const float* src = in + (size_t)plane*NPIX + (size_t)row*HP;
    for (int i = threadIdx.x; i < HP; i += blockDim.x){
        sv[i] = src[i];
        float2 t = g_tw[i];
        sTA[i] = pack2(t.x, t.x);
        sTB[i] = pack2(t.y, t.y);
    }
    if (threadIdx.x < 10){
        float2 t = g_tw[27*threadIdx.x];
        sT10[threadIdx.x] = pack2(t.x, t.y);
    }
    __syncthreads();
    int t = threadIdx.x;
    if (t < HP){
        int n2 = t % 27, k1 = t / 27;
        u64 acc = 0; int idx = 0;
        #pragma unroll
        for (int n1 = 0; n1 < 10; ++n1){
            float s = sv[27*n1 + n2];
            acc = ffma2(pack2(s, s), sT10[idx], acc);
            idx += k1; if (idx >= 10) idx -= 10;
        }
        sG[t] = acc;
    }
    __syncthreads();
    if (t < HP){
        int k1 = t % 10;
        u64 P = 0, Q = 0; int idx = 0;
        #pragma unroll 3
        for (int n2 = 0; n2 < 27; ++n2){
            u64 g = sG[k1*27 + n2];
            P = ffma2(g, sTA[idx], P);
            Q = ffma2(g, sTB[idx], Q);
            idx += t; if (idx >= HP) idx -= HP;
        }
        float2 p = unpack2(P), q = unpack2(Q);
        out[(size_t)plane*NPIX + (size_t)row*HP + t] = make_float2(p.x - q.y, p.y + q.x);
    }
}

// MODE 0: plain; MODE 1: rows ×Hf; MODE 2: rows, full Wiener T product
template<int ROWS, int MODE>
__global__ void k_dft_line_c(const float2* __restrict__ in, float2* __restrict__ out,
                             float sgn, float scale, const float* __restrict__ alpha){
    __shared__ __align__(8) u64 sv[HP];
    __shared__ __align__(8) u64 sTA[HP], sTB[HP], sG[HP];
    int plane = blockIdx.y, line = blockIdx.x;
    int srcplane = (MODE == 2) ? (plane >> 2) : plane;
    const float2* src = in + (size_t)srcplane*NPIX + (ROWS ? (size_t)line*HP : (size_t)line);
    float ad = 0.f;
    if (MODE == 2) ad = expf(alpha[plane & 3]);
    for (int i = threadIdx.x; i < HP; i += blockDim.x){
        float2 v = ROWS ? src[i] : src[(size_t)i*HP];
        if (MODE == 1){
            float2 H = g_Hf[line*HP + i];
            v = make_float2(v.x*H.x - v.y*H.y, v.x*H.y + v.y*H.x);
        } else if (MODE == 2){
            int p = line*HP + i;
            float2 H = g_Hf[p];
            float den = H.x*H.x + H.y*H.y + ad*g_S[p];
            float Tx =  H.x/den, Ty = -H.y/den;
            v = make_float2(Tx*v.x - Ty*v.y, Tx*v.y + Ty*v.x);
        }
        sv[i] = pack2(v.x, v.y);
        float2 t = g_tw[i];
        float ty = sgn*t.y;
        sTA[i] = pack2(t.x, t.x);
        sTB[i] = pack2(ty, ty);
    }
    __syncthreads();
    int t = threadIdx.x;
    if (t < HP){
        int n2 = t % 27, k1 = t / 27;
        u64 PA = 0, QA = 0; int idx = 0;
        #pragma unroll
        for (int n1 = 0; n1 < 10; ++n1){
            u64 s = sv[27*n1 + n2];
            PA = ffma2(s, sTA[27*idx], PA);
            QA = ffma2(s, sTB[27*idx], QA);
            idx += k1; if (idx >= 10) idx -= 10;
        }
        float2 p = unpack2(PA), q = unpack2(QA);
        sG[t] = pack2(p.x - q.y, p.y + q.x);
    }
    __syncthreads();
    if (t < HP){
        int k1 = t % 10;
        u64 P = 0, Q = 0; int idx = 0;
        #pragma unroll 3
        for (int n2 = 0; n2 < 27; ++n2){
            u64 g = sG[k1*27 + n2];
            P = ffma2(g, sTA[idx], P);
            Q = ffma2(g, sTB[idx], Q);
            idx += t; if (idx >= HP) idx -= HP;
        }
        float2 p = unpack2(P), q = unpack2(Q);
        size_t o = (size_t)plane*NPIX + (ROWS ? ((size_t)line*HP + t) : ((size_t)t*HP + line));
        out[o] = make_float2((p.x - q.y)*scale, (p.y + q.x)*scale);
    }
}

// MODE 0: write out; MODE 1: edgetaper blend into g_xp
template<int MODE>
__global__ void k_dft_cols_real(const float2* __restrict__ in, float* __restrict__ out,
                                float sgn, float scale){
    __shared__ __align__(8) u64 sv[HP];
    __shared__ __align__(8) u64 sTA[HP], sTB[HP], sTC[HP], sG[HP];
    int plane = blockIdx.y, col = blockIdx.x;
    const float2* src = in + (size_t)plane*NPIX + col;
    for (int i = threadIdx.x; i < HP; i += blockDim.x){
        float2 v = src[(size_t)i*HP];
        sv[i] = pack2(v.x, v.y);
        float2 t = g_tw[i];
        float ty = sgn*t.y;
        sTA[i] = pack2(t.x, t.x);
        sTB[i] = pack2(ty, ty);
        sTC[i] = pack2(t.x, -ty);
    }
    __syncthreads();
    int t = threadIdx.x;
    if (t < HP){
        int n2 = t % 27, k1 = t / 27;
        u64 PA = 0, QA = 0; int idx = 0;
        #pragma unroll
        for (int n1 = 0; n1 < 10; ++n1){
            u64 s = sv[27*n1 + n2];
            PA = ffma2(s, sTA[27*idx], PA);
            QA = ffma2(s, sTB[27*idx], QA);
            idx += k1; if (idx >= 10) idx -= 10;
        }
        float2 p = unpack2(PA), q = unpack2(QA);
        sG[t] = pack2(p.x - q.y, p.y + q.x);
    }
    __syncthreads();
    if (t < HP){
        int k1 = t % 10;
        u64 acc = 0; int idx = 0;
        #pragma unroll 3
        for (int n2 = 0; n2 < 27; ++n2){
            acc = ffma2(sG[k1*27 + n2], sTC[idx], acc);
            idx += t; if (idx >= HP) idx -= HP;
        }
        float2 a = unpack2(acc);
        float val = (a.x + a.y)*scale;
        size_t o = (size_t)plane*NPIX + (size_t)t*HP + col;
        if (MODE == 1){
            float aa = g_ah[t]*g_aw[col];
            g_xp[o] = aa*g_xp[o] + (1.f - aa)*val;
        } else {
            out[o] = val;
        }
    }
}

__global__ void k_amp(const float* __restrict__ alpha){
    __shared__ float red[256];
    int d = blockIdx.x;
    float ad = expf(alpha[d]);
    float s = 0.f;
    for (int p = threadIdx.x; p < NPIX; p += 256){
        float2 H = g_Hf[p];
        float h2 = H.x*H.x + H.y*H.y;
        float den = h2 + ad*g_S[p];
        s += h2 / (den*den);
    }
    red[threadIdx.x] = s; __syncthreads();
    for (int o = 128; o; o >>= 1){
        if (threadIdx.x < o) red[threadIdx.x] += red[threadIdx.x + o];
        __syncthreads();
    }
    if (threadIdx.x == 0) g_amp[d] = red[0] / (float)NPIX;
}

__global__ void k_cstdn(const float* __restrict__ stdn){
    int n = threadIdx.x;
    if (n < ND){
        int b = n >> 2, d = n & 3;
        g_cstdn[n] = sqrtf(stdn[b]*stdn[b]*g_amp[d]);
    }
}

// ---- conv1 via tf32 mma: taps as K (25 -> 4 chunks of 8) ----------------
__global__ __launch_bounds__(256) void k_conv1_mma(const float* __restrict__ bias){
    __shared__ __align__(16) float s_in[20*36];       // 16x32 tile + 4 halo
    __shared__ __align__(16) float s_a[4*32*12];      // [kc][oc][tap pad12]
    int n  = blockIdx.z;
    int y0 = blockIdx.y*16, x0 = blockIdx.x*32;
    int tid  = threadIdx.x;
    int lane = tid & 31, wp = tid >> 5;
    int gid  = lane >> 2, tig = lane & 3;

    // stage weights [kc][oc][t], zero-padded taps 25..31
    for (int i = tid; i < 4*32*8; i += 256){
        int kc = i >> 8;
        int r  = i & 255;
        int oc = r >> 3, t = r & 7;
        int tap = kc*8 + t;
        s_a[(kc*32 + oc)*12 + t] = (tap < 25) ? f2tf32(g_cw[oc*25 + tap]) : 0.f;
    }
    // stage input 20x36 (halo -2)
    {
        const float* src = g_z + (size_t)n*NPIX;
        bool interior = (y0 >= 2) && (y0 + 18 <= HP) && (x0 >= 2) && (x0 + 34 <= HP);
        if (interior){
            const float* p0 = src + (size_t)(y0-2)*HP + (x0-2);
            for (int i = tid; i < 720; i += 256){
                int r = i / 36, c = i - r*36;
                s_in[i] = f2tf32(p0[r*HP + c]);
            }
        } else {
            for (int i = tid; i < 720; i += 256){
                int r = i / 36, c = i - r*36;
                s_in[i] = f2tf32(src[refl(y0-2+r,HP)*HP + refl(x0-2+c,HP)]);
            }
        }
    }
    __syncthreads();

    float d[2][8][4];
    #pragma unroll
    for (int m = 0; m < 2; ++m){
        float blo = bias[m*16 + gid];
        float bhi = bias[m*16 + gid + 8];
        #pragma unroll
        for (int nt = 0; nt < 8; ++nt){
            d[m][nt][0] = blo; d[m][nt][1] = blo;
            d[m][nt][2] = bhi; d[m][nt][3] = bhi;
        }
    }

    #pragma unroll
    for (int kc = 0; kc < 4; ++kc){
        u32 a[2][4];
        #pragma unroll
        for (int m = 0; m < 2; ++m){
            int base = (kc*32 + m*16 + gid)*12 + tig;
            a[m][0] = __float_as_uint(s_a[base]);
            a[m][1] = __float_as_uint(s_a[base + 8*12]);
            a[m][2] = __float_as_uint(s_a[base + 4]);
            a[m][3] = __float_as_uint(s_a[base + 8*12 + 4]);
        }
        int tap0 = kc*8 + tig;
        int tap1 = tap0 + 4;
        int t0 = (tap0 < 25) ? tap0 : 24;
        int t1 = (tap1 < 25) ? tap1 : 24;
        int ky0 = t0/5, kx0 = t0 - 5*ky0;
        int ky1 = t1/5, kx1 = t1 - 5*ky1;
        #pragma unroll
        for (int nt = 0; nt < 8; ++nt){
            int r  = nt >> 2, c8 = nt & 3;
            int row = 2*wp + r;
            int colb = c8*8 + gid;
            u32 b0 = __float_as_uint(s_in[(row + ky0)*36 + colb + kx0]);
            u32 b1 = __float_as_uint(s_in[(row + ky1)*36 + colb + kx1]);
            #pragma unroll
            for (int m = 0; m < 2; ++m)
                mma_tf32(d[m][nt], a[m], b0, b1);
        }
    }

    #pragma unroll
    for (int m = 0; m < 2; ++m){
        #pragma unroll
        for (int nt = 0; nt < 8; ++nt){
            int r  = nt >> 2, c8 = nt & 3;
            int y = y0 + 2*wp + r;
            int x = x0 + c8*8 + 2*tig;
            if (y < HP && x < HP){
                int oc = m*16 + gid;
                size_t p0 = ((size_t)n*32 + oc)*NPIX + (size_t)y*HP + x;
                size_t p1 = p0 + (size_t)8*NPIX;
                *(float2*)(g_f0 + p0) = make_float2(d[m][nt][0], d[m][nt][1]);
                *(float2*)(g_f0 + p1) = make_float2(d[m][nt][2], d[m][nt][3]);
            }
        }
    }
}

// ---- tf32 mma conv, 16x16 tile, nt=4 (R7 known-good) --------------------
template<int CIN, int COUT>
__global__ __launch_bounds__(256) void k_mma_conv(
    const float* __restrict__ in, const float* __restrict__ wt,
    const float* __restrict__ bias, const float* __restrict__ prelu,
    const float* __restrict__ skip, float* __restrict__ out)
{
    constexpr int MT  = COUT/16;
    constexpr int NCH = CIN/8;
    __shared__ __align__(16) float s_in[8*328];
    __shared__ __align__(16) float w_s[9*COUT*12];

    int n  = blockIdx.z;
    int y0 = blockIdx.y*16, x0 = blockIdx.x*16;
    int tid  = threadIdx.x;
    int lane = tid & 31, wp = tid >> 5;
    int gid  = lane >> 2, tig = lane & 3;

    bool interior = (y0 >= 1) && (y0 <= HP-18) && (x0 >= 1) && (x0 <= HP-18);

    float d[MT][4][4];
    #pragma unroll
    for (int m = 0; m < MT; ++m){
        float blo = bias[m*16 + gid];
        float bhi = bias[m*16 + gid + 8];
        #pragma unroll
        for (int nt = 0; nt < 4; ++nt){
            d[m][nt][0] = blo; d[m][nt][1] = blo;
            d[m][nt][2] = bhi; d[m][nt][3] = bhi;
        }
    }

    const float* inb = in + (size_t)n*CIN*NPIX;
    for (int ck = 0; ck < NCH; ++ck){
        __syncthreads();
        {
            const float4* ws4 = (const float4*)(wt + (size_t)ck*9*COUT*12);
            float4* wd4 = (float4*)w_s;
            for (int i = tid; i < 9*COUT*3; i += 256) wd4[i] = ws4[i];
        }
        {
            int cin = ck*8 + wp;
            const float* src = inb + (size_t)cin*NPIX;
            float sl = prelu[cin];
            float* dst = &s_in[wp*328];
            if (interior){
                const float* p0 = src + (size_t)(y0-1)*HP + (x0-1);
                for (int j = lane; j < 324; j += 32){
                    int yy = j / 18, xx = j - yy*18;
                    float v = p0[yy*HP + xx];
                    dst[j] = f2tf32((v >= 0.f) ? v : v*sl);
                }
            } else {
                for (int j = lane; j < 324; j += 32){
                    int yy = j / 18, xx = j - yy*18;
                    float v = src[refl(y0-1+yy,HP)*HP + refl(x0-1+xx,HP)];
                    dst[j] = f2tf32((v >= 0.f) ? v : v*sl);
                }
            }
        }
        __syncthreads();

        #pragma unroll
        for (int tap = 0; tap < 9; ++tap){
            int ky = tap/3, kx = tap - 3*(tap/3);
            u32 a[MT][4];
            #pragma unroll
            for (int m = 0; m < MT; ++m){
                int base = (tap*COUT + m*16 + gid)*12 + tig;
                a[m][0] = __float_as_uint(w_s[base]);
                a[m][1] = __float_as_uint(w_s[base + 8*12]);
                a[m][2] = __float_as_uint(w_s[base + 4]);
                a[m][3] = __float_as_uint(w_s[base + 8*12 + 4]);
            }
            #pragma unroll
            for (int nt = 0; nt < 4; ++nt){
                int rr  = 2*wp + (nt >> 1);
                int yy  = rr + ky;
                int xxb = (nt & 1)*8 + gid + kx;
                u32 b0 = __float_as_uint(s_in[tig*328 + yy*18 + xxb]);
                u32 b1 = __float_as_uint(s_in[(tig+4)*328 + yy*18 + xxb]);
                #pragma unroll
                for (int m = 0; m < MT; ++m)
                    mma_tf32(d[m][nt], a[m], b0, b1);
            }
        }
    }

    #pragma unroll
    for (int m = 0; m < MT; ++m){
        #pragma unroll
        for (int nt = 0; nt < 4; ++nt){
            int y = y0 + 2*wp + (nt >> 1);
            int x = x0 + (nt & 1)*8 + 2*tig;
            if (y < HP && x < HP){
                int oc = m*16 + gid;
                size_t p0 = ((size_t)n*COUT + oc)*NPIX + (size_t)y*HP + x;
                size_t p1 = p0 + (size_t)8*NPIX;
                float2 v0 = make_float2(d[m][nt][0], d[m][nt][1]);
                float2 v1 = make_float2(d[m][nt][2], d[m][nt][3]);
                if (skip){
                    float2 s0 = *(const float2*)(skip + p0);
                    float2 s1 = *(const float2*)(skip + p1);
                    v0.x += s0.x; v0.y += s0.y;
                    v1.x += s1.x; v1.y += s1.y;
                }
                *(float2*)(out + p0) = v0;
                *(float2*)(out + p1) = v1;
            }
        }
    }
}

__global__ __launch_bounds__(256) void k_convT(const float* __restrict__ in,
                                               const float* __restrict__ biasT){
    __shared__ __align__(8) u64 s_in2[20*20];
    __shared__ __align__(8) u64 s_wp[25];
    int n = blockIdx.z;
    int ty = threadIdx.y, tx = threadIdx.x;
    int tid = ty*16 + tx;
    int y0 = blockIdx.y*16, x0 = blockIdx.x*16;
    u64 acc2 = 0;
    for (int op = 0; op < 16; ++op){
        __syncthreads();
        const float* src0 = in + ((size_t)n*32 + 2*op)*NPIX;
        const float* src1 = src0 + NPIX;
        for (int i = tid; i < 400; i += 256){
            int r = i / 20, c = i - r*20;
            int yy = y0 - 2 + r, xx = x0 - 2 + c;
            if (yy >= 0 && yy < HP && xx >= 0 && xx < HP){
                size_t o = (size_t)yy*HP + xx;
                s_in2[i] = pack2(src0[o], src1[o]);
            } else s_in2[i] = 0;
        }
        if (tid < 25) s_wp[tid] = pack2(g_cw[(2*op)*25 + tid], g_cw[(2*op+1)*25 + tid]);
        __syncthreads();
        #pragma unroll
        for (int u = 0; u < 5; ++u)
            #pragma unroll
            for (int v = 0; v < 5; ++v)
                acc2 = ffma2(s_in2[(ty + 4 - u)*20 + tx + 4 - v], s_wp[u*5 + v], acc2);
    }
    int oy = y0 + ty, ox = x0 + tx;
    if (oy < HP && ox < HP){
        float2 a = unpack2(acc2);
        g_ct[(size_t)n*NPIX + oy*HP + ox] = biasT[0] + a.x + a.y;
    }
}

__global__ void k_nrm(){
    __shared__ float red[256];
    int n = blockIdx.x;
    float s = 0.f;
    for (int p = threadIdx.x; p < NPIX; p += 256){
        float v = g_ct[(size_t)n*NPIX + p];
        s += v*v;
    }
    red[threadIdx.x] = s; __syncthreads();
    for (int o = 128; o; o >>= 1){
        if (threadIdx.x < o) red[threadIdx.x] += red[threadIdx.x + o];
        __syncthreads();
    }
    if (threadIdx.x == 0) g_nrm2[n] = red[0];
}

__global__ void k_scl(const float* __restrict__ ap){
    int n = threadIdx.x;
    if (n < ND){
        float eps = expf(ap[0]) * g_cstdn[n] * sqrtf((float)(NPIX - 1));
        float nr  = sqrtf(g_nrm2[n]);
        g_scl[n] = (nr > eps) ? eps / fmaxf(nr, 1e-12f) : 1.f;
    }
}

__global__ void k_final(const float* __restrict__ mw, float* __restrict__ outp){
    int b = blockIdx.y;
    int p = blockIdx.x*256 + threadIdx.x;
    int y = p >> 8, x = p & 255;
    size_t q = (size_t)(y + 7)*HP + (x + 7);
    float acc = 0.f;
    #pragma unroll
    for (int d = 0; d < 4; ++d){
        int n = b*4 + d;
        float r = g_z[(size_t)n*NPIX + q] - g_ct[(size_t)n*NPIX + q]*g_scl[n];
        r = fminf(fmaxf(r, 0.f), 255.f);
        acc += mw[d]*r;
    }
    outp[(size_t)b*65536 + p] = acc;
}

extern "C" void kernel_launch(void* const* d_in, const int* in_sizes, int n_in,
                              void* d_out, int out_size){
    const float* x      = (const float*)d_in[0];
    const float* bk     = (const float*)d_in[1];
    const float* stdn   = (const float*)d_in[2];
    const float* wienw  = (const float*)d_in[3];
    const float* wiensc = (const float*)d_in[4];
    const float* alpha  = (const float*)d_in[5];
    const float* convw  = (const float*)d_in[6];
    const float* scalef = (const float*)d_in[7];
    const float* biasf  = (const float*)d_in[8];
    const float* biast  = (const float*)d_in[9];
    const float* p1     = (const float*)d_in[10];
    const float* w1     = (const float*)d_in[11];
    const float* s1     = (const float*)d_in[12];
    const float* b1     = (const float*)d_in[13];
    const float* p2     = (const float*)d_in[14];
    const float* w2     = (const float*)d_in[15];
    const float* s2     = (const float*)d_in[16];
    const float* b2     = (const float*)d_in[17];
    const float* aproj  = (const float*)d_in[18];
    const float* mw     = (const float*)d_in[19];
    float* outp = (float*)d_out;

    float *pxp, *pz, *pww, *pcw, *pw1, *pw2, *pw1t, *pw2t, *pf0, *pf1;
    float2 *pX, *pT1;
    cudaGetSymbolAddress((void**)&pxp, g_xp);
    cudaGetSymbolAddress((void**)&pz,  g_z);
    cudaGetSymbolAddress((void**)&pww, g_ww);
    cudaGetSymbolAddress((void**)&pcw, g_cw);
    cudaGetSymbolAddress((void**)&pw1, g_w1);
    cudaGetSymbolAddress((void**)&pw2, g_w2);
    cudaGetSymbolAddress((void**)&pw1t, g_w1t);
    cudaGetSymbolAddress((void**)&pw2t, g_w2t);
    cudaGetSymbolAddress((void**)&pf0, g_f0);
    cudaGetSymbolAddress((void**)&pf1, g_f1);
    cudaGetSymbolAddress((void**)&pX,  g_X);
    cudaGetSymbolAddress((void**)&pT1, g_T1);

    const int PB = (NPIX + 255)/256;
    const float INV = 1.0f/(float)HP;

    k_init_tw<<<1, 288>>>();
    k_wnorm<<<24, 32>>>(wienw, wiensc, pww, 25);
    k_wnorm<<<32, 32>>>(convw, scalef, pcw, 25);
    k_wnorm<<<320, 32>>>(w1, s1, pw1, 288);
    k_wnorm<<<160, 32>>>(w2, s2, pw2, 576);
    k_wprep<32,64><<<dim3(72,5), 256>>>(pw1, pw1t);
    k_wprep<64,32><<<dim3(72,5), 256>>>(pw2, pw2t);

    k_pad<<<dim3(PB, NB), 256>>>(x);
    k_alphas<<<1, 288>>>(bk);
    k_psf1<<<(HP*15 + 255)/256, 256>>>(bk);
    k_psf2<<<PB, 256>>>();
    k_wien1<<<(24*HP*5 + 255)/256, 256>>>();
    k_S<<<PB, 256>>>();

    // fft2(xp) -> X
    k_dft_rows_real<<<dim3(HP, NB), 288>>>(pxp, pT1);
    k_dft_line_c<0,0><<<dim3(HP, NB), 288>>>(pT1, pX, 1.f, 1.f, nullptr);
    // edgetaper: ifft2(X*Hf).real blended into xp (fused)
    k_dft_line_c<1,1><<<dim3(HP, NB), 288>>>(pX, pT1, -1.f, INV, nullptr);
    k_dft_cols_real<1><<<dim3(HP, NB), 288>>>(pT1, nullptr, -1.f, INV);

    // Y = fft2(xp) -> X
    k_dft_rows_real<<<dim3(HP, NB), 288>>>(pxp, pT1);
    k_dft_line_c<0,0><<<dim3(HP, NB), 288>>>(pT1, pX, 1.f, 1.f, nullptr);

    k_amp<<<4, 256>>>(alpha);
    k_cstdn<<<1, 32>>>(stdn);

    // z = ifft2(T * Y).real (Wiener product fused)
    k_dft_line_c<1,2><<<dim3(HP, ND), 288>>>(pX, pT1, -1.f, INV, alpha);
    k_dft_cols_real<0><<<dim3(HP, ND), 288>>>(pT1, pz, -1.f, INV);

    // CNN
    k_conv1_mma<<<dim3(9,17,ND), 256>>>(biasf);
    for (int i = 0; i < 5; ++i){
        k_mma_conv<32,64><<<dim3(17,17,ND), 256>>>(
            pf0, pw1t + (size_t)i*4*9*64*12, b1 + i*64, p1 + i*32, nullptr, pf1);
        k_mma_conv<64,32><<<dim3(17,17,ND), 256>>>(
            pf1, pw2t + (size_t)i*8*9*32*12, b2 + i*32, p2 + i*64,
            (i == 0) ? pf0 : nullptr, pf0);
    }
    k_convT<<<dim3(17,17,ND), dim3(16,16)>>>(pf0, biast);

    k_nrm<<<ND, 256>>>();
    k_scl<<<1, 32>>>(aproj);
    k_final<<<dim3(256, NB), 256>>>(mw, outp);
}

// round 14
// speedup vs baseline: 2.0110x; 1.1954x over previous
#include <cuda_runtime.h>
#include <cuda_fp16.h>
#include <math.h>

#define HP   270
#define NPIX 72900
#define NB   2
#define ND   8
#define HIN  256

typedef unsigned long long u64;
typedef unsigned int u32;

__device__ float  g_xp[NB*NPIX];
__device__ float2 g_X [NB*NPIX];
__device__ float2 g_T1[ND*NPIX];
__device__ float2 g_Hf[NPIX];
__device__ float  g_S [NPIX];
__device__ float2 g_tw[HP];
__device__ float2 g_tempB[HP*15];
__device__ float2 g_tempG[24*HP*5];
__device__ float  g_ah[HP];
__device__ float  g_aw[HP];
__device__ float  g_z [ND*NPIX];
__device__ float  g_ww[24*25];
__device__ float  g_cw[32*25];
__device__ float  g_w1[5*64*32*9];
__device__ float  g_w2[5*32*64*9];
__device__ __align__(16) u32 g_w1h[5*2*9*64*12];
__device__ __align__(16) u32 g_w2h[5*4*9*32*12];
__device__ float  g_f0[ND*32*NPIX];
__device__ float  g_f1[ND*64*NPIX];
__device__ float  g_ct[ND*NPIX];
__device__ float  g_amp[4];
__device__ float  g_cstdn[ND];
__device__ float  g_nrm2[ND];
__device__ float  g_scl[ND];

static __device__ __forceinline__ int refl(int i, int n){
    if (i < 0)  i = -i - 1;
    if (i >= n) i = 2*n - 1 - i;
    return i;
}

static __device__ __forceinline__ u64 pack2(float lo, float hi){
    u64 r;
    asm("mov.b64 %0, {%1, %2};" : "=l"(r) : "f"(lo), "f"(hi));
    return r;
}
static __device__ __forceinline__ u64 ffma2(u64 a, u64 b, u64 c){
    u64 d;
    asm("fma.rn.f32x2 %0, %1, %2, %3;" : "=l"(d) : "l"(a), "l"(b), "l"(c));
    return d;
}
static __device__ __forceinline__ float2 unpack2(u64 v){
    float lo, hi;
    asm("mov.b64 {%0, %1}, %2;" : "=f"(lo), "=f"(hi) : "l"(v));
    return make_float2(lo, hi);
}
static __device__ __forceinline__ float f2tf32(float v){
    u32 u;
    asm("cvt.rna.tf32.f32 %0, %1;" : "=r"(u) : "f"(v));
    return __uint_as_float(u);
}
static __device__ __forceinline__ u32 h2pack(float a, float b){
    __half2 h = __floats2half2_rn(a, b);
    return *reinterpret_cast<u32*>(&h);
}
static __device__ __forceinline__ void mma_tf32(float* d, const u32* a, u32 b0, u32 b1){
    asm volatile(
        "mma.sync.aligned.m16n8k8.row.col.f32.tf32.tf32.f32 "
        "{%0,%1,%2,%3}, {%4,%5,%6,%7}, {%8,%9}, {%0,%1,%2,%3};"
        : "+f"(d[0]), "+f"(d[1]), "+f"(d[2]), "+f"(d[3])
        : "r"(a[0]), "r"(a[1]), "r"(a[2]), "r"(a[3]), "r"(b0), "r"(b1));
}
static __device__ __forceinline__ void mma_f16(float* d, const u32* a, u32 b0, u32 b1){
    asm volatile(
        "mma.sync.aligned.m16n8k16.row.col.f32.f16.f16.f32 "
        "{%0,%1,%2,%3}, {%4,%5,%6,%7}, {%8,%9}, {%0,%1,%2,%3};"
        : "+f"(d[0]), "+f"(d[1]), "+f"(d[2]), "+f"(d[3])
        : "r"(a[0]), "r"(a[1]), "r"(a[2]), "r"(a[3]), "r"(b0), "r"(b1));
}

__global__ void k_init_tw(){
    int t = threadIdx.x;
    if (t < HP){
        double ang = -2.0 * 3.14159265358979323846 * (double)t / (double)HP;
        double s, c; sincos(ang, &s, &c);
        g_tw[t] = make_float2((float)c, (float)s);
    }
}

__global__ void k_pad(const float* __restrict__ x){
    int p = blockIdx.x*256 + threadIdx.x;
    if (p >= NPIX) return;
    int b = blockIdx.y;
    int y = p / HP, xx = p - y*HP;
    g_xp[b*NPIX + p] = x[b*HIN*HIN + refl(y-7,HIN)*HIN + refl(xx-7,HIN)];
}

__global__ void k_alphas(const float* __restrict__ bk){
    __shared__ float ph[15], pw[15], rh[15], rw[15];
    int t = threadIdx.x;
    if (t < 15){
        float s = 0.f, q = 0.f;
        for (int j = 0; j < 15; ++j){ s += bk[t*15+j]; q += bk[j*15+t]; }
        ph[t] = s; pw[t] = q;
    }
    __syncthreads();
    if (t < 15){
        float s = 0.f, q = 0.f;
        for (int j = 0; j + t < 15; ++j){ s += ph[j]*ph[j+t]; q += pw[j]*pw[j+t]; }
        rh[t] = s; rw[t] = q;
    }
    __syncthreads();
    if (t < HP){
        float zh = 0.f, zw = 0.f;
        if (t <= 14)       { zh = rh[t];       zw = rw[t];       }
        else if (t >= 255) { zh = rh[269 - t]; zw = rw[269 - t]; }
        g_ah[t] = 1.f - zh / rh[0];
        g_aw[t] = 1.f - zw / rw[0];
    }
}

__global__ void k_psf1(const float* __restrict__ bk){
    int tid = blockIdx.x*256 + threadIdx.x;
    if (tid >= HP*15) return;
    int u = tid / 15, w = tid - u*15;
    float ax = 0.f, ay = 0.f;
    for (int h = 0; h < 15; ++h){
        int rr = (h >= 7) ? (h - 7) : (h + 263);
        float2 t = g_tw[(u*rr) % HP];
        float v = bk[h*15 + w];
        ax += v*t.x; ay += v*t.y;
    }
    g_tempB[tid] = make_float2(ax, ay);
}

__global__ void k_psf2(){
    int p = blockIdx.x*256 + threadIdx.x;
    if (p >= NPIX) return;
    int u = p / HP, v = p - u*HP;
    float ax = 0.f, ay = 0.f;
    for (int w = 0; w < 15; ++w){
        int rr = (w >= 7) ? (w - 7) : (w + 263);
        float2 t = g_tw[(v*rr) % HP];
        float2 b = g_tempB[u*15 + w];
        ax += b.x*t.x - b.y*t.y;
        ay += b.x*t.y + b.y*t.x;
    }
    g_Hf[p] = make_float2(ax, ay);
}

__global__ void k_wnorm(const float* __restrict__ w, const float* __restrict__ sc,
                        float* __restrict__ out, int sz){
    int ch = blockIdx.x;
    const float* src = w + (size_t)ch*sz;
    int lane = threadIdx.x;
    float s = 0.f;
    for (int i = lane; i < sz; i += 32) s += src[i];
    #pragma unroll
    for (int o = 16; o; o >>= 1) s += __shfl_xor_sync(0xffffffffu, s, o);
    float mean = s / (float)sz;
    float q = 0.f;
    for (int i = lane; i < sz; i += 32){ float v = src[i]-mean; q += v*v; }
    #pragma unroll
    for (int o = 16; o; o >>= 1) q += __shfl_xor_sync(0xffffffffu, q, o);
    float inv = sc[ch] / sqrtf(q);
    for (int i = lane; i < sz; i += 32) out[(size_t)ch*sz + i] = (src[i]-mean)*inv;
}

// pack normalized weights to half2 k-pairs: [layer][ck16][tap][oc][12 half2]
template<int CIN, int COUT>
__global__ void k_wpreph(const float* __restrict__ wn, u32* __restrict__ dst){
    int layer = blockIdx.y;
    const float* w = wn + (size_t)layer*COUT*CIN*9;
    u32* d = dst + (size_t)layer*(CIN/16)*9*COUT*12;
    int total = (CIN/16)*9*COUT*12;
    for (int i = blockIdx.x*256 + threadIdx.x; i < total; i += gridDim.x*256){
        int ck  = i / (9*COUT*12);
        int r   = i - ck*9*COUT*12;
        int tap = r / (COUT*12);
        int r2  = r - tap*(COUT*12);
        int oc  = r2 / 12, j = r2 - oc*12;
        u32 val = 0;
        if (j < 8){
            int cin = ck*16 + 2*j;
            val = h2pack(w[((size_t)oc*CIN + cin)*9 + tap],
                         w[((size_t)oc*CIN + cin + 1)*9 + tap]);
        }
        d[i] = val;
    }
}

__global__ void k_wien1(){
    int tid = blockIdx.x*256 + threadIdx.x;
    if (tid >= 24*HP*5) return;
    int o = tid / (HP*5);
    int r = tid - o*HP*5;
    int u = r / 5, w = r - u*5;
    float ax = 0.f, ay = 0.f;
    for (int h = 0; h < 5; ++h){
        int rr = (h >= 2) ? (h - 2) : (h + 268);
        float2 t = g_tw[(u*rr) % HP];
        float v = g_ww[o*25 + h*5 + w];
        ax += v*t.x; ay += v*t.y;
    }
    g_tempG[tid] = make_float2(ax, ay);
}

__global__ void k_S(){
    int p = blockIdx.x*256 + threadIdx.x;
    if (p >= NPIX) return;
    int u = p / HP, v = p - u*HP;
    float2 tws[5];
    #pragma unroll
    for (int w = 0; w < 5; ++w){
        int rr = (w >= 2) ? (w - 2) : (w + 268);
        tws[w] = g_tw[(v*rr) % HP];
    }
    float s = 0.f;
    for (int o = 0; o < 24; ++o){
        float ax = 0.f, ay = 0.f;
        int base = (o*HP + u)*5;
        #pragma unroll
        for (int w = 0; w < 5; ++w){
            float2 g = g_tempG[base + w];
            float2 t = tws[w];
            ax += g.x*t.x - g.y*t.y;
            ay += g.x*t.y + g.y*t.x;
        }
        s += ax*ax + ay*ay;
    }
    g_S[p] = s;
}

// ===== Cooley-Tukey 270 = 27x10 DFT line kernels ======================

__global__ void k_dft_rows_real(const float* __restrict__ in, float2* __restrict__ out){
    __shared__ float sv[HP];
    __shared__ __align__(8) u64 sTA[HP], sTB[HP], sT10[10], sG[HP];
    int plane = blockIdx.y, row = blockIdx.x;
    const float* src = in + (size_t)plane*NPIX + (size_t)row*HP;
    for (int i = threadIdx.x; i < HP; i += blockDim.x){
        sv[i] = src[i];
        float2 t = g_tw[i];
        sTA[i] = pack2(t.x, t.x);
        sTB[i] = pack2(t.y, t.y);
    }
    if (threadIdx.x < 10){
        float2 t = g_tw[27*threadIdx.x];
        sT10[threadIdx.x] = pack2(t.x, t.y);
    }
    __syncthreads();
    int t = threadIdx.x;
    if (t < HP){
        int n2 = t % 27, k1 = t / 27;
        u64 acc = 0; int idx = 0;
        #pragma unroll
        for (int n1 = 0; n1 < 10; ++n1){
            float s = sv[27*n1 + n2];
            acc = ffma2(pack2(s, s), sT10[idx], acc);
            idx += k1; if (idx >= 10) idx -= 10;
        }
        sG[t] = acc;
    }
    __syncthreads();
    if (t < HP){
        int k1 = t % 10;
        u64 P = 0, Q = 0; int idx = 0;
        #pragma unroll 3
        for (int n2 = 0; n2 < 27; ++n2){
            u64 g = sG[k1*27 + n2];
            P = ffma2(g, sTA[idx], P);
            Q = ffma2(g, sTB[idx], Q);
            idx += t; if (idx >= HP) idx -= HP;
        }
        float2 p = unpack2(P), q = unpack2(Q);
        out[(size_t)plane*NPIX + (size_t)row*HP + t] = make_float2(p.x - q.y, p.y + q.x);
    }
}

// MODE 0: plain; MODE 1: rows ×Hf; MODE 2: rows, full Wiener T product
template<int ROWS, int MODE>
__global__ void k_dft_line_c(const float2* __restrict__ in, float2* __restrict__ out,
                             float sgn, float scale, const float* __restrict__ alpha){
    __shared__ __align__(8) u64 sv[HP];
    __shared__ __align__(8) u64 sTA[HP], sTB[HP], sG[HP];
    int plane = blockIdx.y, line = blockIdx.x;
    int srcplane = (MODE == 2) ? (plane >> 2) : plane;
    const float2* src = in + (size_t)srcplane*NPIX + (ROWS ? (size_t)line*HP : (size_t)line);
    float ad = 0.f;
    if (MODE == 2) ad = expf(alpha[plane & 3]);
    for (int i = threadIdx.x; i < HP; i += blockDim.x){
        float2 v = ROWS ? src[i] : src[(size_t)i*HP];
        if (MODE == 1){
            float2 H = g_Hf[line*HP + i];
            v = make_float2(v.x*H.x - v.y*H.y, v.x*H.y + v.y*H.x);
        } else if (MODE == 2){
            int p = line*HP + i;
            float2 H = g_Hf[p];
            float den = H.x*H.x + H.y*H.y + ad*g_S[p];
            float Tx =  H.x/den, Ty = -H.y/den;
            v = make_float2(Tx*v.x - Ty*v.y, Tx*v.y + Ty*v.x);
        }
        sv[i] = pack2(v.x, v.y);
        float2 t = g_tw[i];
        float ty = sgn*t.y;
        sTA[i] = pack2(t.x, t.x);
        sTB[i] = pack2(ty, ty);
    }
    __syncthreads();
    int t = threadIdx.x;
    if (t < HP){
        int n2 = t % 27, k1 = t / 27;
        u64 PA = 0, QA = 0; int idx = 0;
        #pragma unroll
        for (int n1 = 0; n1 < 10; ++n1){
            u64 s = sv[27*n1 + n2];
            PA = ffma2(s, sTA[27*idx], PA);
            QA = ffma2(s, sTB[27*idx], QA);
            idx += k1; if (idx >= 10) idx -= 10;
        }
        float2 p = unpack2(PA), q = unpack2(QA);
        sG[t] = pack2(p.x - q.y, p.y + q.x);
    }
    __syncthreads();
    if (t < HP){
        int k1 = t % 10;
        u64 P = 0, Q = 0; int idx = 0;
        #pragma unroll 3
        for (int n2 = 0; n2 < 27; ++n2){
            u64 g = sG[k1*27 + n2];
            P = ffma2(g, sTA[idx], P);
            Q = ffma2(g, sTB[idx], Q);
            idx += t; if (idx >= HP) idx -= HP;
        }
        float2 p = unpack2(P), q = unpack2(Q);
        size_t o = (size_t)plane*NPIX + (ROWS ? ((size_t)line*HP + t) : ((size_t)t*HP + line));
        out[o] = make_float2((p.x - q.y)*scale, (p.y + q.x)*scale);
    }
}

// MODE 0: write out; MODE 1: edgetaper blend into g_xp
template<int MODE>
__global__ void k_dft_cols_real(const float2* __restrict__ in, float* __restrict__ out,
                                float sgn, float scale){
    __shared__ __align__(8) u64 sv[HP];
    __shared__ __align__(8) u64 sTA[HP], sTB[HP], sTC[HP], sG[HP];
    int plane = blockIdx.y, col = blockIdx.x;
    const float2* src = in + (size_t)plane*NPIX + col;
    for (int i = threadIdx.x; i < HP; i += blockDim.x){
        float2 v = src[(size_t)i*HP];
        sv[i] = pack2(v.x, v.y);
        float2 t = g_tw[i];
        float ty = sgn*t.y;
        sTA[i] = pack2(t.x, t.x);
        sTB[i] = pack2(ty, ty);
        sTC[i] = pack2(t.x, -ty);
    }
    __syncthreads();
    int t = threadIdx.x;
    if (t < HP){
        int n2 = t % 27, k1 = t / 27;
        u64 PA = 0, QA = 0; int idx = 0;
        #pragma unroll
        for (int n1 = 0; n1 < 10; ++n1){
            u64 s = sv[27*n1 + n2];
            PA = ffma2(s, sTA[27*idx], PA);
            QA = ffma2(s, sTB[27*idx], QA);
            idx += k1; if (idx >= 10) idx -= 10;
        }
        float2 p = unpack2(PA), q = unpack2(QA);
        sG[t] = pack2(p.x - q.y, p.y + q.x);
    }
    __syncthreads();
    if (t < HP){
        int k1 = t % 10;
        u64 acc = 0; int idx = 0;
        #pragma unroll 3
        for (int n2 = 0; n2 < 27; ++n2){
            acc = ffma2(sG[k1*27 + n2], sTC[idx], acc);
            idx += t; if (idx >= HP) idx -= HP;
        }
        float2 a = unpack2(acc);
        float val = (a.x + a.y)*scale;
        size_t o = (size_t)plane*NPIX + (size_t)t*HP + col;
        if (MODE == 1){
            float aa = g_ah[t]*g_aw[col];
            g_xp[o] = aa*g_xp[o] + (1.f - aa)*val;
        } else {
            out[o] = val;
        }
    }
}

__global__ void k_amp(const float* __restrict__ alpha){
    __shared__ float red[256];
    int d = blockIdx.x;
    float ad = expf(alpha[d]);
    float s = 0.f;
    for (int p = threadIdx.x; p < NPIX; p += 256){
        float2 H = g_Hf[p];
        float h2 = H.x*H.x + H.y*H.y;
        float den = h2 + ad*g_S[p];
        s += h2 / (den*den);
    }
    red[threadIdx.x] = s; __syncthreads();
    for (int o = 128; o; o >>= 1){
        if (threadIdx.x < o) red[threadIdx.x] += red[threadIdx.x + o];
        __syncthreads();
    }
    if (threadIdx.x == 0) g_amp[d] = red[0] / (float)NPIX;
}

__global__ void k_cstdn(const float* __restrict__ stdn){
    int n = threadIdx.x;
    if (n < ND){
        int b = n >> 2, d = n & 3;
        g_cstdn[n] = sqrtf(stdn[b]*stdn[b]*g_amp[d]);
    }
}

// ---- conv1 via tf32 mma: taps as K (25 -> 4 chunks of 8) ----------------
__global__ __launch_bounds__(256) void k_conv1_mma(const float* __restrict__ bias){
    __shared__ __align__(16) float s_in[20*36];
    __shared__ __align__(16) float s_a[4*32*12];
    int n  = blockIdx.z;
    int y0 = blockIdx.y*16, x0 = blockIdx.x*32;
    int tid  = threadIdx.x;
    int lane = tid & 31, wp = tid >> 5;
    int gid  = lane >> 2, tig = lane & 3;

    for (int i = tid; i < 4*32*8; i += 256){
        int kc = i >> 8;
        int r  = i & 255;
        int oc = r >> 3, t = r & 7;
        int tap = kc*8 + t;
        s_a[(kc*32 + oc)*12 + t] = (tap < 25) ? f2tf32(g_cw[oc*25 + tap]) : 0.f;
    }
    {
        const float* src = g_z + (size_t)n*NPIX;
        bool interior = (y0 >= 2) && (y0 + 18 <= HP) && (x0 >= 2) && (x0 + 34 <= HP);
        if (interior){
            const float* p0 = src + (size_t)(y0-2)*HP + (x0-2);
            for (int i = tid; i < 720; i += 256){
                int r = i / 36, c = i - r*36;
                s_in[i] = f2tf32(p0[r*HP + c]);
            }
        } else {
            for (int i = tid; i < 720; i += 256){
                int r = i / 36, c = i - r*36;
                s_in[i] = f2tf32(src[refl(y0-2+r,HP)*HP + refl(x0-2+c,HP)]);
            }
        }
    }
    __syncthreads();

    float d[2][8][4];
    #pragma unroll
    for (int m = 0; m < 2; ++m){
        float blo = bias[m*16 + gid];
        float bhi = bias[m*16 + gid + 8];
        #pragma unroll
        for (int nt = 0; nt < 8; ++nt){
            d[m][nt][0] = blo; d[m][nt][1] = blo;
            d[m][nt][2] = bhi; d[m][nt][3] = bhi;
        }
    }

    #pragma unroll
    for (int kc = 0; kc < 4; ++kc){
        u32 a[2][4];
        #pragma unroll
        for (int m = 0; m < 2; ++m){
            int base = (kc*32 + m*16 + gid)*12 + tig;
            a[m][0] = __float_as_uint(s_a[base]);
            a[m][1] = __float_as_uint(s_a[base + 8*12]);
            a[m][2] = __float_as_uint(s_a[base + 4]);
            a[m][3] = __float_as_uint(s_a[base + 8*12 + 4]);
        }
        int tap0 = kc*8 + tig;
        int tap1 = tap0 + 4;
        int t0 = (tap0 < 25) ? tap0 : 24;
        int t1 = (tap1 < 25) ? tap1 : 24;
        int ky0 = t0/5, kx0 = t0 - 5*ky0;
        int ky1 = t1/5, kx1 = t1 - 5*ky1;
        #pragma unroll
        for (int nt = 0; nt < 8; ++nt){
            int r  = nt >> 2, c8 = nt & 3;
            int row = 2*wp + r;
            int colb = c8*8 + gid;
            u32 b0 = __float_as_uint(s_in[(row + ky0)*36 + colb + kx0]);
            u32 b1 = __float_as_uint(s_in[(row + ky1)*36 + colb + kx1]);
            #pragma unroll
            for (int m = 0; m < 2; ++m)
                mma_tf32(d[m][nt], a[m], b0, b1);
        }
    }

    #pragma unroll
    for (int m = 0; m < 2; ++m){
        #pragma unroll
        for (int nt = 0; nt < 8; ++nt){
            int r  = nt >> 2, c8 = nt & 3;
            int y = y0 + 2*wp + r;
            int x = x0 + c8*8 + 2*tig;
            if (y < HP && x < HP){
                int oc = m*16 + gid;
                size_t p0 = ((size_t)n*32 + oc)*NPIX + (size_t)y*HP + x;
                size_t p1 = p0 + (size_t)8*NPIX;
                *(float2*)(g_f0 + p0) = make_float2(d[m][nt][0], d[m][nt][1]);
                *(float2*)(g_f0 + p1) = make_float2(d[m][nt][2], d[m][nt][3]);
            }
        }
    }
}

// ---- fp16 mma conv (m16n8k16): 16x16 tile, K = 16 cin per chunk ---------
template<int CIN, int COUT>
__global__ __launch_bounds__(256) void k_mma_conv(
    const float* __restrict__ in, const u32* __restrict__ wt,
    const float* __restrict__ bias, const float* __restrict__ prelu,
    const float* __restrict__ skip, float* __restrict__ out)
{
    constexpr int MT  = COUT/16;
    constexpr int NCH = CIN/16;
    __shared__ __align__(16) u32 s_in[8*328];      // [kpair][18x18], half2
    __shared__ __align__(16) u32 w_s[9*COUT*12];   // [tap][oc][12 half2 pad]

    int n  = blockIdx.z;
    int y0 = blockIdx.y*16, x0 = blockIdx.x*16;
    int tid  = threadIdx.x;
    int lane = tid & 31, wp = tid >> 5;
    int gid  = lane >> 2, tig = lane & 3;

    bool interior = (y0 >= 1) && (y0 <= HP-18) && (x0 >= 1) && (x0 <= HP-18);

    float d[MT][4][4];
    #pragma unroll
    for (int m = 0; m < MT; ++m){
        float blo = bias[m*16 + gid];
        float bhi = bias[m*16 + gid + 8];
        #pragma unroll
        for (int nt = 0; nt < 4; ++nt){
            d[m][nt][0] = blo; d[m][nt][1] = blo;
            d[m][nt][2] = bhi; d[m][nt][3] = bhi;
        }
    }

    const float* inb = in + (size_t)n*CIN*NPIX;
    for (int ck = 0; ck < NCH; ++ck){
        __syncthreads();
        {
            const uint4* ws4 = (const uint4*)(wt + (size_t)ck*9*COUT*12);
            uint4* wd4 = (uint4*)w_s;
            for (int i = tid; i < 9*COUT*3; i += 256) wd4[i] = ws4[i];
        }
        {
            int cin0 = ck*16 + 2*wp;
            const float* src0 = inb + (size_t)cin0*NPIX;
            const float* src1 = src0 + NPIX;
            float sl0 = prelu[cin0], sl1 = prelu[cin0+1];
            u32* dst = &s_in[wp*328];
            if (interior){
                size_t off = (size_t)(y0-1)*HP + (x0-1);
                const float* p0 = src0 + off;
                const float* p1 = src1 + off;
                for (int j = lane; j < 324; j += 32){
                    int yy = j / 18, xx = j - yy*18;
                    float v0 = p0[yy*HP + xx];
                    float v1 = p1[yy*HP + xx];
                    v0 = (v0 >= 0.f) ? v0 : v0*sl0;
                    v1 = (v1 >= 0.f) ? v1 : v1*sl1;
                    dst[j] = h2pack(v0, v1);
                }
            } else {
                for (int j = lane; j < 324; j += 32){
                    int yy = j / 18, xx = j - yy*18;
                    size_t off = (size_t)refl(y0-1+yy,HP)*HP + refl(x0-1+xx,HP);
                    float v0 = src0[off];
                    float v1 = src1[off];
                    v0 = (v0 >= 0.f) ? v0 : v0*sl0;
                    v1 = (v1 >= 0.f) ? v1 : v1*sl1;
                    dst[j] = h2pack(v0, v1);
                }
            }
        }
        __syncthreads();

        #pragma unroll
        for (int tap = 0; tap < 9; ++tap){
            int ky = tap/3, kx = tap - 3*(tap/3);
            u32 a[MT][4];
            #pragma unroll
            for (int m = 0; m < MT; ++m){
                int base = (tap*COUT + m*16 + gid)*12 + tig;
                a[m][0] = w_s[base];
                a[m][1] = w_s[base + 8*12];
                a[m][2] = w_s[base + 4];
                a[m][3] = w_s[base + 8*12 + 4];
            }
            #pragma unroll
            for (int nt = 0; nt < 4; ++nt){
                int rr  = 2*wp + (nt >> 1);
                int yy  = rr + ky;
                int xxb = (nt & 1)*8 + gid + kx;
                u32 b0 = s_in[tig*328 + yy*18 + xxb];
                u32 b1 = s_in[(tig+4)*328 + yy*18 + xxb];
                #pragma unroll
                for (int m = 0; m < MT; ++m)
                    mma_f16(d[m][nt], a[m], b0, b1);
            }
        }
    }

    #pragma unroll
    for (int m = 0; m < MT; ++m){
        #pragma unroll
        for (int nt = 0; nt < 4; ++nt){
            int y = y0 + 2*wp + (nt >> 1);
            int x = x0 + (nt & 1)*8 + 2*tig;
            if (y < HP && x < HP){
                int oc = m*16 + gid;
                size_t p0 = ((size_t)n*COUT + oc)*NPIX + (size_t)y*HP + x;
                size_t p1 = p0 + (size_t)8*NPIX;
                float2 v0 = make_float2(d[m][nt][0], d[m][nt][1]);
                float2 v1 = make_float2(d[m][nt][2], d[m][nt][3]);
                if (skip){
                    float2 s0 = *(const float2*)(skip + p0);
                    float2 s1 = *(const float2*)(skip + p1);
                    v0.x += s0.x; v0.y += s0.y;
                    v1.x += s1.x; v1.y += s1.y;
                }
                *(float2*)(out + p0) = v0;
                *(float2*)(out + p1) = v1;
            }
        }
    }
}

__global__ __launch_bounds__(256) void k_convT(const float* __restrict__ in,
                                               const float* __restrict__ biasT){
    __shared__ __align__(8) u64 s_in2[20*20];
    __shared__ __align__(8) u64 s_wp[25];
    int n = blockIdx.z;
    int ty = threadIdx.y, tx = threadIdx.x;
    int tid = ty*16 + tx;
    int y0 = blockIdx.y*16, x0 = blockIdx.x*16;
    u64 acc2 = 0;
    for (int op = 0; op < 16; ++op){
        __syncthreads();
        const float* src0 = in + ((size_t)n*32 + 2*op)*NPIX;
        const float* src1 = src0 + NPIX;
        for (int i = tid; i < 400; i += 256){
            int r = i / 20, c = i - r*20;
            int yy = y0 - 2 + r, xx = x0 - 2 + c;
            if (yy >= 0 && yy < HP && xx >= 0 && xx < HP){
                size_t o = (size_t)yy*HP + xx;
                s_in2[i] = pack2(src0[o], src1[o]);
            } else s_in2[i] = 0;
        }
        if (tid < 25) s_wp[tid] = pack2(g_cw[(2*op)*25 + tid], g_cw[(2*op+1)*25 + tid]);
        __syncthreads();
        #pragma unroll
        for (int u = 0; u < 5; ++u)
            #pragma unroll
            for (int v = 0; v < 5; ++v)
                acc2 = ffma2(s_in2[(ty + 4 - u)*20 + tx + 4 - v], s_wp[u*5 + v], acc2);
    }
    int oy = y0 + ty, ox = x0 + tx;
    if (oy < HP && ox < HP){
        float2 a = unpack2(acc2);
        g_ct[(size_t)n*NPIX + oy*HP + ox] = biasT[0] + a.x + a.y;
    }
}

__global__ void k_nrm(){
    __shared__ float red[256];
    int n = blockIdx.x;
    float s = 0.f;
    for (int p = threadIdx.x; p < NPIX; p += 256){
        float v = g_ct[(size_t)n*NPIX + p];
        s += v*v;
    }
    red[threadIdx.x] = s; __syncthreads();
    for (int o = 128; o; o >>= 1){
        if (threadIdx.x < o) red[threadIdx.x] += red[threadIdx.x + o];
        __syncthreads();
    }
    if (threadIdx.x == 0) g_nrm2[n] = red[0];
}

__global__ void k_scl(const float* __restrict__ ap){
    int n = threadIdx.x;
    if (n < ND){
        float eps = expf(ap[0]) * g_cstdn[n] * sqrtf((float)(NPIX - 1));
        float nr  = sqrtf(g_nrm2[n]);
        g_scl[n] = (nr > eps) ? eps / fmaxf(nr, 1e-12f) : 1.f;
    }
}

__global__ void k_final(const float* __restrict__ mw, float* __restrict__ outp){
    int b = blockIdx.y;
    int p = blockIdx.x*256 + threadIdx.x;
    int y = p >> 8, x = p & 255;
    size_t q = (size_t)(y + 7)*HP + (x + 7);
    float acc = 0.f;
    #pragma unroll
    for (int d = 0; d < 4; ++d){
        int n = b*4 + d;
        float r = g_z[(size_t)n*NPIX + q] - g_ct[(size_t)n*NPIX + q]*g_scl[n];
        r = fminf(fmaxf(r, 0.f), 255.f);
        acc += mw[d]*r;
    }
    outp[(size_t)b*65536 + p] = acc;
}

extern "C" void kernel_launch(void* const* d_in, const int* in_sizes, int n_in,
                              void* d_out, int out_size){
    const float* x      = (const float*)d_in[0];
    const float* bk     = (const float*)d_in[1];
    const float* stdn   = (const float*)d_in[2];
    const float* wienw  = (const float*)d_in[3];
    const float* wiensc = (const float*)d_in[4];
    const float* alpha  = (const float*)d_in[5];
    const float* convw  = (const float*)d_in[6];
    const float* scalef = (const float*)d_in[7];
    const float* biasf  = (const float*)d_in[8];
    const float* biast  = (const float*)d_in[9];
    const float* p1     = (const float*)d_in[10];
    const float* w1     = (const float*)d_in[11];
    const float* s1     = (const float*)d_in[12];
    const float* b1     = (const float*)d_in[13];
    const float* p2     = (const float*)d_in[14];
    const float* w2     = (const float*)d_in[15];
    const float* s2     = (const float*)d_in[16];
    const float* b2     = (const float*)d_in[17];
    const float* aproj  = (const float*)d_in[18];
    const float* mw     = (const float*)d_in[19];
    float* outp = (float*)d_out;

    float *pxp, *pz, *pww, *pcw, *pw1, *pw2, *pf0, *pf1;
    u32 *pw1h, *pw2h;
    float2 *pX, *pT1;
    cudaGetSymbolAddress((void**)&pxp, g_xp);
    cudaGetSymbolAddress((void**)&pz,  g_z);
    cudaGetSymbolAddress((void**)&pww, g_ww);
    cudaGetSymbolAddress((void**)&pcw, g_cw);
    cudaGetSymbolAddress((void**)&pw1, g_w1);
    cudaGetSymbolAddress((void**)&pw2, g_w2);
    cudaGetSymbolAddress((void**)&pw1h, g_w1h);
    cudaGetSymbolAddress((void**)&pw2h, g_w2h);
    cudaGetSymbolAddress((void**)&pf0, g_f0);
    cudaGetSymbolAddress((void**)&pf1, g_f1);
    cudaGetSymbolAddress((void**)&pX,  g_X);
    cudaGetSymbolAddress((void**)&pT1, g_T1);

    const int PB = (NPIX + 255)/256;
    const float INV = 1.0f/(float)HP;

    // ordering chosen so ncu's capture window (-s 5) lands on a DFT kernel
    k_init_tw<<<1, 288>>>();                                   // 1
    k_pad<<<dim3(PB, NB), 256>>>(x);                           // 2
    k_alphas<<<1, 288>>>(bk);                                  // 3
    k_psf1<<<(HP*15 + 255)/256, 256>>>(bk);                    // 4
    k_psf2<<<PB, 256>>>();                                     // 5
    // fft2(xp) -> X
    k_dft_rows_real<<<dim3(HP, NB), 288>>>(pxp, pT1);          // 6 (captured)
    k_dft_line_c<0,0><<<dim3(HP, NB), 288>>>(pT1, pX, 1.f, 1.f, nullptr);
    // edgetaper: ifft2(X*Hf).real blended into xp (fused)
    k_dft_line_c<1,1><<<dim3(HP, NB), 288>>>(pX, pT1, -1.f, INV, nullptr);
    k_dft_cols_real<1><<<dim3(HP, NB), 288>>>(pT1, nullptr, -1.f, INV);

    k_wnorm<<<24, 32>>>(wienw, wiensc, pww, 25);
    k_wnorm<<<32, 32>>>(convw, scalef, pcw, 25);
    k_wnorm<<<320, 32>>>(w1, s1, pw1, 288);
    k_wnorm<<<160, 32>>>(w2, s2, pw2, 576);
    k_wpreph<32,64><<<dim3(54,5), 256>>>(pw1, pw1h);
    k_wpreph<64,32><<<dim3(54,5), 256>>>(pw2, pw2h);
    k_wien1<<<(24*HP*5 + 255)/256, 256>>>();
    k_S<<<PB, 256>>>();

    // Y = fft2(xp) -> X
    k_dft_rows_real<<<dim3(HP, NB), 288>>>(pxp, pT1);
    k_dft_line_c<0,0><<<dim3(HP, NB), 288>>>(pT1, pX, 1.f, 1.f, nullptr);

    k_amp<<<4, 256>>>(alpha);
    k_cstdn<<<1, 32>>>(stdn);

    // z = ifft2(T * Y).real (Wiener product fused)
    k_dft_line_c<1,2><<<dim3(HP, ND), 288>>>(pX, pT1, -1.f, INV, alpha);
    k_dft_cols_real<0><<<dim3(HP, ND), 288>>>(pT1, pz, -1.f, INV);

    // CNN
    k_conv1_mma<<<dim3(9,17,ND), 256>>>(biasf);
    for (int i = 0; i < 5; ++i){
        k_mma_conv<32,64><<<dim3(17,17,ND), 256>>>(
            pf0, pw1h + (size_t)i*2*9*64*12, b1 + i*64, p1 + i*32, nullptr, pf1);
        k_mma_conv<64,32><<<dim3(17,17,ND), 256>>>(
            pf1, pw2h + (size_t)i*4*9*32*12, b2 + i*32, p2 + i*64,
            (i == 0) ? pf0 : nullptr, pf0);
    }
    k_convT<<<dim3(17,17,ND), dim3(16,16)>>>(pf0, biast);

    k_nrm<<<ND, 256>>>();
    k_scl<<<1, 32>>>(aproj);
    k_final<<<dim3(256, NB), 256>>>(mw, outp);
}

// round 16
// speedup vs baseline: 2.6101x; 1.2979x over previous
#include <cuda_runtime.h>
#include <cuda_fp16.h>
#include <math.h>

#define HP   270
#define NPIX 72900
#define NB   2
#define ND   8
#define HIN  256

typedef unsigned long long u64;
typedef unsigned int u32;

__device__ float  g_xp[NB*NPIX];
__device__ float2 g_X [NB*NPIX];
__device__ float2 g_T1[ND*NPIX];
__device__ float2 g_Hf[NPIX];
__device__ float  g_S [NPIX];
__device__ float2 g_tw[HP];
__device__ float2 g_tempB[HP*15];
__device__ float2 g_tempG[24*HP*5];
__device__ float  g_ah[HP];
__device__ float  g_aw[HP];
__device__ float  g_z [ND*NPIX];
__device__ float  g_ww[24*25];
__device__ float  g_cw[32*25];
__device__ float  g_w1[5*64*32*9];
__device__ float  g_w2[5*32*64*9];
__device__ __align__(16) u32 g_w1h[5*2*9*64*12];
__device__ __align__(16) u32 g_w2h[5*4*9*32*12];
__device__ float  g_f0[ND*32*NPIX];
__device__ float  g_f1[ND*64*NPIX];
__device__ float  g_ct[ND*NPIX];
__device__ float  g_amp[4];
__device__ float  g_cstdn[ND];
__device__ float  g_nrm2[ND];
__device__ float  g_scl[ND];

static __device__ __forceinline__ int refl(int i, int n){
    if (i < 0)  i = -i - 1;
    if (i >= n) i = 2*n - 1 - i;
    return i;
}

static __device__ __forceinline__ u64 pack2(float lo, float hi){
    u64 r;
    asm("mov.b64 %0, {%1, %2};" : "=l"(r) : "f"(lo), "f"(hi));
    return r;
}
static __device__ __forceinline__ u64 ffma2(u64 a, u64 b, u64 c){
    u64 d;
    asm("fma.rn.f32x2 %0, %1, %2, %3;" : "=l"(d) : "l"(a), "l"(b), "l"(c));
    return d;
}
static __device__ __forceinline__ float2 unpack2(u64 v){
    float lo, hi;
    asm("mov.b64 {%0, %1}, %2;" : "=f"(lo), "=f"(hi) : "l"(v));
    return make_float2(lo, hi);
}
static __device__ __forceinline__ float f2tf32(float v){
    u32 u;
    asm("cvt.rna.tf32.f32 %0, %1;" : "=r"(u) : "f"(v));
    return __uint_as_float(u);
}
static __device__ __forceinline__ u32 h2pack(float a, float b){
    __half2 h = __floats2half2_rn(a, b);
    return *reinterpret_cast<u32*>(&h);
}
static __device__ __forceinline__ void mma_tf32(float* d, const u32* a, u32 b0, u32 b1){
    asm volatile(
        "mma.sync.aligned.m16n8k8.row.col.f32.tf32.tf32.f32 "
        "{%0,%1,%2,%3}, {%4,%5,%6,%7}, {%8,%9}, {%0,%1,%2,%3};"
        : "+f"(d[0]), "+f"(d[1]), "+f"(d[2]), "+f"(d[3])
        : "r"(a[0]), "r"(a[1]), "r"(a[2]), "r"(a[3]), "r"(b0), "r"(b1));
}
static __device__ __forceinline__ void mma_f16(float* d, const u32* a, u32 b0, u32 b1){
    asm volatile(
        "mma.sync.aligned.m16n8k16.row.col.f32.f16.f16.f32 "
        "{%0,%1,%2,%3}, {%4,%5,%6,%7}, {%8,%9}, {%0,%1,%2,%3};"
        : "+f"(d[0]), "+f"(d[1]), "+f"(d[2]), "+f"(d[3])
        : "r"(a[0]), "r"(a[1]), "r"(a[2]), "r"(a[3]), "r"(b0), "r"(b1));
}

__global__ void k_init_tw(){
    int t = threadIdx.x;
    if (t < HP){
        double ang = -2.0 * 3.14159265358979323846 * (double)t / (double)HP;
        double s, c; sincos(ang, &s, &c);
        g_tw[t] = make_float2((float)c, (float)s);
    }
}

__global__ void k_pad(const float* __restrict__ x){
    int p = blockIdx.x*256 + threadIdx.x;
    if (p >= NPIX) return;
    int b = blockIdx.y;
    int y = p / HP, xx = p - y*HP;
    g_xp[b*NPIX + p] = x[b*HIN*HIN + refl(y-7,HIN)*HIN + refl(xx-7,HIN)];
}

__global__ void k_alphas(const float* __restrict__ bk){
    __shared__ float ph[15], pw[15], rh[15], rw[15];
    int t = threadIdx.x;
    if (t < 15){
        float s = 0.f, q = 0.f;
        for (int j = 0; j < 15; ++j){ s += bk[t*15+j]; q += bk[j*15+t]; }
        ph[t] = s; pw[t] = q;
    }
    __syncthreads();
    if (t < 15){
        float s = 0.f, q = 0.f;
        for (int j = 0; j + t < 15; ++j){ s += ph[j]*ph[j+t]; q += pw[j]*pw[j+t]; }
        rh[t] = s; rw[t] = q;
    }
    __syncthreads();
    if (t < HP){
        float zh = 0.f, zw = 0.f;
        if (t <= 14)       { zh = rh[t];       zw = rw[t];       }
        else if (t >= 255) { zh = rh[269 - t]; zw = rw[269 - t]; }
        g_ah[t] = 1.f - zh / rh[0];
        g_aw[t] = 1.f - zw / rw[0];
    }
}

__global__ void k_psf1(const float* __restrict__ bk){
    int tid = blockIdx.x*256 + threadIdx.x;
    if (tid >= HP*15) return;
    int u = tid / 15, w = tid - u*15;
    float ax = 0.f, ay = 0.f;
    for (int h = 0; h < 15; ++h){
        int rr = (h >= 7) ? (h - 7) : (h + 263);
        float2 t = g_tw[(u*rr) % HP];
        float v = bk[h*15 + w];
        ax += v*t.x; ay += v*t.y;
    }
    g_tempB[tid] = make_float2(ax, ay);
}

__global__ void k_psf2(){
    int p = blockIdx.x*256 + threadIdx.x;
    if (p >= NPIX) return;
    int u = p / HP, v = p - u*HP;
    float ax = 0.f, ay = 0.f;
    for (int w = 0; w < 15; ++w){
        int rr = (w >= 7) ? (w - 7) : (w + 263);
        float2 t = g_tw[(v*rr) % HP];
        float2 b = g_tempB[u*15 + w];
        ax += b.x*t.x - b.y*t.y;
        ay += b.x*t.y + b.y*t.x;
    }
    g_Hf[p] = make_float2(ax, ay);
}

__global__ void k_wnorm(const float* __restrict__ w, const float* __restrict__ sc,
                        float* __restrict__ out, int sz){
    int ch = blockIdx.x;
    const float* src = w + (size_t)ch*sz;
    int lane = threadIdx.x;
    float s = 0.f;
    for (int i = lane; i < sz; i += 32) s += src[i];
    #pragma unroll
    for (int o = 16; o; o >>= 1) s += __shfl_xor_sync(0xffffffffu, s, o);
    float mean = s / (float)sz;
    float q = 0.f;
    for (int i = lane; i < sz; i += 32){ float v = src[i]-mean; q += v*v; }
    #pragma unroll
    for (int o = 16; o; o >>= 1) q += __shfl_xor_sync(0xffffffffu, q, o);
    float inv = sc[ch] / sqrtf(q);
    for (int i = lane; i < sz; i += 32) out[(size_t)ch*sz + i] = (src[i]-mean)*inv;
}

// pack normalized weights to half2 k-pairs: [layer][ck16][tap][oc][12 half2]
template<int CIN, int COUT>
__global__ void k_wpreph(const float* __restrict__ wn, u32* __restrict__ dst){
    int layer = blockIdx.y;
    const float* w = wn + (size_t)layer*COUT*CIN*9;
    u32* d = dst + (size_t)layer*(CIN/16)*9*COUT*12;
    int total = (CIN/16)*9*COUT*12;
    for (int i = blockIdx.x*256 + threadIdx.x; i < total; i += gridDim.x*256){
        int ck  = i / (9*COUT*12);
        int r   = i - ck*9*COUT*12;
        int tap = r / (COUT*12);
        int r2  = r - tap*(COUT*12);
        int oc  = r2 / 12, j = r2 - oc*12;
        u32 val = 0;
        if (j < 8){
            int cin = ck*16 + 2*j;
            val = h2pack(w[((size_t)oc*CIN + cin)*9 + tap],
                         w[((size_t)oc*CIN + cin + 1)*9 + tap]);
        }
        d[i] = val;
    }
}

__global__ void k_wien1(){
    int tid = blockIdx.x*256 + threadIdx.x;
    if (tid >= 24*HP*5) return;
    int o = tid / (HP*5);
    int r = tid - o*HP*5;
    int u = r / 5, w = r - u*5;
    float ax = 0.f, ay = 0.f;
    for (int h = 0; h < 5; ++h){
        int rr = (h >= 2) ? (h - 2) : (h + 268);
        float2 t = g_tw[(u*rr) % HP];
        float v = g_ww[o*25 + h*5 + w];
        ax += v*t.x; ay += v*t.y;
    }
    g_tempG[tid] = make_float2(ax, ay);
}

__global__ void k_S(){
    int p = blockIdx.x*256 + threadIdx.x;
    if (p >= NPIX) return;
    int u = p / HP, v = p - u*HP;
    float2 tws[5];
    #pragma unroll
    for (int w = 0; w < 5; ++w){
        int rr = (w >= 2) ? (w - 2) : (w + 268);
        tws[w] = g_tw[(v*rr) % HP];
    }
    float s = 0.f;
    for (int o = 0; o < 24; ++o){
        float ax = 0.f, ay = 0.f;
        int base = (o*HP + u)*5;
        #pragma unroll
        for (int w = 0; w < 5; ++w){
            float2 g = g_tempG[base + w];
            float2 t = tws[w];
            ax += g.x*t.x - g.y*t.y;
            ay += g.x*t.y + g.y*t.x;
        }
        s += ax*ax + ay*ay;
    }
    g_S[p] = s;
}

// ===== Cooley-Tukey 270 = 27x10 DFT line kernels ======================

__global__ void k_dft_rows_real(const float* __restrict__ in, float2* __restrict__ out){
    __shared__ float sv[HP];
    __shared__ __align__(8) u64 sTA[HP], sTB[HP], sT10[10], sG[HP];
    int plane = blockIdx.y, row = blockIdx.x;
    const float* src = in + (size_t)plane*NPIX + (size_t)row*HP;
    for (int i = threadIdx.x; i < HP; i += blockDim.x){
        sv[i] = src[i];
        float2 t = g_tw[i];
        sTA[i] = pack2(t.x, t.x);
        sTB[i] = pack2(t.y, t.y);
    }
    if (threadIdx.x < 10){
        float2 t = g_tw[27*threadIdx.x];
        sT10[threadIdx.x] = pack2(t.x, t.y);
    }
    __syncthreads();
    int t = threadIdx.x;
    if (t < HP){
        int n2 = t % 27, k1 = t / 27;
        u64 acc = 0; int idx = 0;
        #pragma unroll
        for (int n1 = 0; n1 < 10; ++n1){
            float s = sv[27*n1 + n2];
            acc = ffma2(pack2(s, s), sT10[idx], acc);
            idx += k1; if (idx >= 10) idx -= 10;
        }
        sG[t] = acc;
    }
    __syncthreads();
    if (t < HP){
        int k1 = t % 10;
        u64 P = 0, Q = 0; int idx = 0;
        #pragma unroll 3
        for (int n2 = 0; n2 < 27; ++n2){
            u64 g = sG[k1*27 + n2];
            P = ffma2(g, sTA[idx], P);
            Q = ffma2(g, sTB[idx], Q);
            idx += t; if (idx >= HP) idx -= HP;
        }
        float2 p = unpack2(P), q = unpack2(Q);
        out[(size_t)plane*NPIX + (size_t)row*HP + t] = make_float2(p.x - q.y, p.y + q.x);
    }
}

// MODE 0: plain; MODE 1: rows ×Hf; MODE 2: rows, full Wiener T product
template<int ROWS, int MODE>
__global__ void k_dft_line_c(const float2* __restrict__ in, float2* __restrict__ out,
                             float sgn, float scale, const float* __restrict__ alpha){
    __shared__ __align__(8) u64 sv[HP];
    __shared__ __align__(8) u64 sTA[HP], sTB[HP], sG[HP];
    int plane = blockIdx.y, line = blockIdx.x;
    int srcplane = (MODE == 2) ? (plane >> 2) : plane;
    const float2* src = in + (size_t)srcplane*NPIX + (ROWS ? (size_t)line*HP : (size_t)line);
    float ad = 0.f;
    if (MODE == 2) ad = expf(alpha[plane & 3]);
    for (int i = threadIdx.x; i < HP; i += blockDim.x){
        float2 v = ROWS ? src[i] : src[(size_t)i*HP];
        if (MODE == 1){
            float2 H = g_Hf[line*HP + i];
            v = make_float2(v.x*H.x - v.y*H.y, v.x*H.y + v.y*H.x);
        } else if (MODE == 2){
            int p = line*HP + i;
            float2 H = g_Hf[p];
            float den = H.x*H.x + H.y*H.y + ad*g_S[p];
            float Tx =  H.x/den, Ty = -H.y/den;
            v = make_float2(Tx*v.x - Ty*v.y, Tx*v.y + Ty*v.x);
        }
        sv[i] = pack2(v.x, v.y);
        float2 t = g_tw[i];
        float ty = sgn*t.y;
        sTA[i] = pack2(t.x, t.x);
        sTB[i] = pack2(ty, ty);
    }
    __syncthreads();
    int t = threadIdx.x;
    if (t < HP){
        int n2 = t % 27, k1 = t / 27;
        u64 PA = 0, QA = 0; int idx = 0;
        #pragma unroll
        for (int n1 = 0; n1 < 10; ++n1){
            u64 s = sv[27*n1 + n2];
            PA = ffma2(s, sTA[27*idx], PA);
            QA = ffma2(s, sTB[27*idx], QA);
            idx += k1; if (idx >= 10) idx -= 10;
        }
        float2 p = unpack2(PA), q = unpack2(QA);
        sG[t] = pack2(p.x - q.y, p.y + q.x);
    }
    __syncthreads();
    if (t < HP){
        int k1 = t % 10;
        u64 P = 0, Q = 0; int idx = 0;
        #pragma unroll 3
        for (int n2 = 0; n2 < 27; ++n2){
            u64 g = sG[k1*27 + n2];
            P = ffma2(g, sTA[idx], P);
            Q = ffma2(g, sTB[idx], Q);
            idx += t; if (idx >= HP) idx -= HP;
        }
        float2 p = unpack2(P), q = unpack2(Q);
        size_t o = (size_t)plane*NPIX + (ROWS ? ((size_t)line*HP + t) : ((size_t)t*HP + line));
        out[o] = make_float2((p.x - q.y)*scale, (p.y + q.x)*scale);
    }
}

// MODE 0: write out; MODE 1: edgetaper blend into g_xp
template<int MODE>
__global__ void k_dft_cols_real(const float2* __restrict__ in, float* __restrict__ out,
                                float sgn, float scale){
    __shared__ __align__(8) u64 sv[HP];
    __shared__ __align__(8) u64 sTA[HP], sTB[HP], sTC[HP], sG[HP];
    int plane = blockIdx.y, col = blockIdx.x;
    const float2* src = in + (size_t)plane*NPIX + col;
    for (int i = threadIdx.x; i < HP; i += blockDim.x){
        float2 v = src[(size_t)i*HP];
        sv[i] = pack2(v.x, v.y);
        float2 t = g_tw[i];
        float ty = sgn*t.y;
        sTA[i] = pack2(t.x, t.x);
        sTB[i] = pack2(ty, ty);
        sTC[i] = pack2(t.x, -ty);
    }
    __syncthreads();
    int t = threadIdx.x;
    if (t < HP){
        int n2 = t % 27, k1 = t / 27;
        u64 PA = 0, QA = 0; int idx = 0;
        #pragma unroll
        for (int n1 = 0; n1 < 10; ++n1){
            u64 s = sv[27*n1 + n2];
            PA = ffma2(s, sTA[27*idx], PA);
            QA = ffma2(s, sTB[27*idx], QA);
            idx += k1; if (idx >= 10) idx -= 10;
        }
        float2 p = unpack2(PA), q = unpack2(QA);
        sG[t] = pack2(p.x - q.y, p.y + q.x);
    }
    __syncthreads();
    if (t < HP){
        int k1 = t % 10;
        u64 acc = 0; int idx = 0;
        #pragma unroll 3
        for (int n2 = 0; n2 < 27; ++n2){
            acc = ffma2(sG[k1*27 + n2], sTC[idx], acc);
            idx += t; if (idx >= HP) idx -= HP;
        }
        float2 a = unpack2(acc);
        float val = (a.x + a.y)*scale;
        size_t o = (size_t)plane*NPIX + (size_t)t*HP + col;
        if (MODE == 1){
            float aa = g_ah[t]*g_aw[col];
            g_xp[o] = aa*g_xp[o] + (1.f - aa)*val;
        } else {
            out[o] = val;
        }
    }
}

__global__ void k_amp(const float* __restrict__ alpha){
    __shared__ float red[256];
    int d = blockIdx.x;
    float ad = expf(alpha[d]);
    float s = 0.f;
    for (int p = threadIdx.x; p < NPIX; p += 256){
        float2 H = g_Hf[p];
        float h2 = H.x*H.x + H.y*H.y;
        float den = h2 + ad*g_S[p];
        s += h2 / (den*den);
    }
    red[threadIdx.x] = s; __syncthreads();
    for (int o = 128; o; o >>= 1){
        if (threadIdx.x < o) red[threadIdx.x] += red[threadIdx.x + o];
        __syncthreads();
    }
    if (threadIdx.x == 0) g_amp[d] = red[0] / (float)NPIX;
}

__global__ void k_cstdn(const float* __restrict__ stdn){
    int n = threadIdx.x;
    if (n < ND){
        int b = n >> 2, d = n & 3;
        g_cstdn[n] = sqrtf(stdn[b]*stdn[b]*g_amp[d]);
    }
}

// ---- conv1 via tf32 mma: taps as K (25 -> 4 chunks of 8) ----------------
__global__ __launch_bounds__(256) void k_conv1_mma(const float* __restrict__ bias){
    __shared__ __align__(16) float s_in[20*36];
    __shared__ __align__(16) float s_a[4*32*12];
    int n  = blockIdx.z;
    int y0 = blockIdx.y*16, x0 = blockIdx.x*32;
    int tid  = threadIdx.x;
    int lane = tid & 31, wp = tid >> 5;
    int gid  = lane >> 2, tig = lane & 3;

    for (int i = tid; i < 4*32*8; i += 256){
        int kc = i >> 8;
        int r  = i & 255;
        int oc = r >> 3, t = r & 7;
        int tap = kc*8 + t;
        s_a[(kc*32 + oc)*12 + t] = (tap < 25) ? f2tf32(g_cw[oc*25 + tap]) : 0.f;
    }
    {
        const float* src = g_z + (size_t)n*NPIX;
        bool interior = (y0 >= 2) && (y0 + 18 <= HP) && (x0 >= 2) && (x0 + 34 <= HP);
        if (interior){
            const float* p0 = src + (size_t)(y0-2)*HP + (x0-2);
            for (int i = tid; i < 720; i += 256){
                int r = i / 36, c = i - r*36;
                s_in[i] = f2tf32(p0[r*HP + c]);
            }
        } else {
            for (int i = tid; i < 720; i += 256){
                int r = i / 36, c = i - r*36;
                s_in[i] = f2tf32(src[refl(y0-2+r,HP)*HP + refl(x0-2+c,HP)]);
            }
        }
    }
    __syncthreads();

    float d[2][8][4];
    #pragma unroll
    for (int m = 0; m < 2; ++m){
        float blo = bias[m*16 + gid];
        float bhi = bias[m*16 + gid + 8];
        #pragma unroll
        for (int nt = 0; nt < 8; ++nt){
            d[m][nt][0] = blo; d[m][nt][1] = blo;
            d[m][nt][2] = bhi; d[m][nt][3] = bhi;
        }
    }

    #pragma unroll
    for (int kc = 0; kc < 4; ++kc){
        u32 a[2][4];
        #pragma unroll
        for (int m = 0; m < 2; ++m){
            int base = (kc*32 + m*16 + gid)*12 + tig;
            a[m][0] = __float_as_uint(s_a[base]);
            a[m][1] = __float_as_uint(s_a[base + 8*12]);
            a[m][2] = __float_as_uint(s_a[base + 4]);
            a[m][3] = __float_as_uint(s_a[base + 8*12 + 4]);
        }
        int tap0 = kc*8 + tig;
        int tap1 = tap0 + 4;
        int t0 = (tap0 < 25) ? tap0 : 24;
        int t1 = (tap1 < 25) ? tap1 : 24;
        int ky0 = t0/5, kx0 = t0 - 5*ky0;
        int ky1 = t1/5, kx1 = t1 - 5*ky1;
        #pragma unroll
        for (int nt = 0; nt < 8; ++nt){
            int r  = nt >> 2, c8 = nt & 3;
            int row = 2*wp + r;
            int colb = c8*8 + gid;
            u32 b0 = __float_as_uint(s_in[(row + ky0)*36 + colb + kx0]);
            u32 b1 = __float_as_uint(s_in[(row + ky1)*36 + colb + kx1]);
            #pragma unroll
            for (int m = 0; m < 2; ++m)
                mma_tf32(d[m][nt], a[m], b0, b1);
        }
    }

    #pragma unroll
    for (int m = 0; m < 2; ++m){
        #pragma unroll
        for (int nt = 0; nt < 8; ++nt){
            int r  = nt >> 2, c8 = nt & 3;
            int y = y0 + 2*wp + r;
            int x = x0 + c8*8 + 2*tig;
            if (y < HP && x < HP){
                int oc = m*16 + gid;
                size_t p0 = ((size_t)n*32 + oc)*NPIX + (size_t)y*HP + x;
                size_t p1 = p0 + (size_t)8*NPIX;
                *(float2*)(g_f0 + p0) = make_float2(d[m][nt][0], d[m][nt][1]);
                *(float2*)(g_f0 + p1) = make_float2(d[m][nt][2], d[m][nt][3]);
            }
        }
    }
}

// ---- fp16 mma conv (m16n8k16), software-pipelined staging ---------------
// dynamic smem: w_s[NCH*9*COUT*12] (all chunks) + s_in[8*328]
template<int CIN, int COUT>
__global__ __launch_bounds__(256,2) void k_mma_conv(
    const float* __restrict__ in, const u32* __restrict__ wt,
    const float* __restrict__ bias, const float* __restrict__ prelu,
    const float* __restrict__ skip, float* __restrict__ out)
{
    constexpr int MT  = COUT/16;
    constexpr int NCH = CIN/16;
    extern __shared__ __align__(16) u32 dynsm[];
    u32* w_s  = dynsm;                       // NCH*9*COUT*12
    u32* s_in = dynsm + NCH*9*COUT*12;       // 8*328

    int n  = blockIdx.z;
    int y0 = blockIdx.y*16, x0 = blockIdx.x*16;
    int tid  = threadIdx.x;
    int lane = tid & 31, wp = tid >> 5;
    int gid  = lane >> 2, tig = lane & 3;

    bool interior = (y0 >= 1) && (y0 <= HP-18) && (x0 >= 1) && (x0 <= HP-18);

    // stage ALL weights once
    {
        const uint4* ws4 = (const uint4*)wt;
        uint4* wd4 = (uint4*)w_s;
        for (int i = tid; i < NCH*9*COUT*3; i += 256) wd4[i] = ws4[i];
    }

    float d[MT][4][4];
    #pragma unroll
    for (int m = 0; m < MT; ++m){
        float blo = bias[m*16 + gid];
        float bhi = bias[m*16 + gid + 8];
        #pragma unroll
        for (int nt = 0; nt < 4; ++nt){
            d[m][nt][0] = blo; d[m][nt][1] = blo;
            d[m][nt][2] = bhi; d[m][nt][3] = bhi;
        }
    }

    const float* inb = in + (size_t)n*CIN*NPIX;

    float pv0[11], pv1[11];
    auto prefetch = [&](int ck){
        int cin0 = ck*16 + 2*wp;
        const float* src0 = inb + (size_t)cin0*NPIX;
        const float* src1 = src0 + NPIX;
        if (interior){
            size_t off = (size_t)(y0-1)*HP + (x0-1);
            const float* p0 = src0 + off;
            const float* p1 = src1 + off;
            #pragma unroll
            for (int it = 0; it < 11; ++it){
                int j = lane + it*32;
                if (j < 324){
                    int yy = j / 18, xx = j - yy*18;
                    pv0[it] = p0[yy*HP + xx];
                    pv1[it] = p1[yy*HP + xx];
                }
            }
        } else {
            #pragma unroll
            for (int it = 0; it < 11; ++it){
                int j = lane + it*32;
                if (j < 324){
                    int yy = j / 18, xx = j - yy*18;
                    size_t off = (size_t)refl(y0-1+yy,HP)*HP + refl(x0-1+xx,HP);
                    pv0[it] = src0[off];
                    pv1[it] = src1[off];
                }
            }
        }
    };
    prefetch(0);

    for (int ck = 0; ck < NCH; ++ck){
        __syncthreads();      // consumers of previous s_in done (also covers w_s first time)
        {
            int cin0 = ck*16 + 2*wp;
            float sl0 = prelu[cin0], sl1 = prelu[cin0+1];
            u32* dst = &s_in[wp*328];
            #pragma unroll
            for (int it = 0; it < 11; ++it){
                int j = lane + it*32;
                if (j < 324){
                    float v0 = pv0[it]; v0 = (v0 >= 0.f) ? v0 : v0*sl0;
                    float v1 = pv1[it]; v1 = (v1 >= 0.f) ? v1 : v1*sl1;
                    dst[j] = h2pack(v0, v1);
                }
            }
        }
        if (ck + 1 < NCH) prefetch(ck + 1);
        __syncthreads();

        #pragma unroll
        for (int tap = 0; tap < 9; ++tap){
            int ky = tap/3, kx = tap - 3*(tap/3);
            u32 a[MT][4];
            #pragma unroll
            for (int m = 0; m < MT; ++m){
                int base = ((ck*9 + tap)*COUT + m*16 + gid)*12 + tig;
                a[m][0] = w_s[base];
                a[m][1] = w_s[base + 8*12];
                a[m][2] = w_s[base + 4];
                a[m][3] = w_s[base + 8*12 + 4];
            }
            #pragma unroll
            for (int nt = 0; nt < 4; ++nt){
                int rr  = 2*wp + (nt >> 1);
                int yy  = rr + ky;
                int xxb = (nt & 1)*8 + gid + kx;
                u32 b0 = s_in[tig*328 + yy*18 + xxb];
                u32 b1 = s_in[(tig+4)*328 + yy*18 + xxb];
                #pragma unroll
                for (int m = 0; m < MT; ++m)
                    mma_f16(d[m][nt], a[m], b0, b1);
            }
        }
    }

    #pragma unroll
    for (int m = 0; m < MT; ++m){
        #pragma unroll
        for (int nt = 0; nt < 4; ++nt){
            int y = y0 + 2*wp + (nt >> 1);
            int x = x0 + (nt & 1)*8 + 2*tig;
            if (y < HP && x < HP){
                int oc = m*16 + gid;
                size_t p0 = ((size_t)n*COUT + oc)*NPIX + (size_t)y*HP + x;
                size_t p1 = p0 + (size_t)8*NPIX;
                float2 v0 = make_float2(d[m][nt][0], d[m][nt][1]);
                float2 v1 = make_float2(d[m][nt][2], d[m][nt][3]);
                if (skip){
                    float2 s0 = *(const float2*)(skip + p0);
                    float2 s1 = *(const float2*)(skip + p1);
                    v0.x += s0.x; v0.y += s0.y;
                    v1.x += s1.x; v1.y += s1.y;
                }
                *(float2*)(out + p0) = v0;
                *(float2*)(out + p1) = v1;
            }
        }
    }
}

// convT with register-prefetch pipelining over the 16 oc-pair stages
__global__ __launch_bounds__(256) void k_convT(const float* __restrict__ in,
                                               const float* __restrict__ biasT){
    __shared__ __align__(8) u64 s_in2[20*20];
    __shared__ __align__(8) u64 s_wp[25];
    int n = blockIdx.z;
    int ty = threadIdx.y, tx = threadIdx.x;
    int tid = ty*16 + tx;
    int y0 = blockIdx.y*16, x0 = blockIdx.x*16;

    float a0, b0, a1, b1, wv0, wv1;
    auto pre = [&](int op){
        const float* src0 = in + ((size_t)n*32 + 2*op)*NPIX;
        const float* src1 = src0 + NPIX;
        {
            int r = tid / 20, c = tid - r*20;
            int yy = y0 - 2 + r, xx = x0 - 2 + c;
            bool ok = (yy >= 0 && yy < HP && xx >= 0 && xx < HP);
            size_t o = ok ? ((size_t)yy*HP + xx) : 0;
            a0 = ok ? src0[o] : 0.f;
            b0 = ok ? src1[o] : 0.f;
        }
        {
            int i = tid + 256;
            if (i < 400){
                int r = i / 20, c = i - r*20;
                int yy = y0 - 2 + r, xx = x0 - 2 + c;
                bool ok = (yy >= 0 && yy < HP && xx >= 0 && xx < HP);
                size_t o = ok ? ((size_t)yy*HP + xx) : 0;
                a1 = ok ? src0[o] : 0.f;
                b1 = ok ? src1[o] : 0.f;
            }
        }
        if (tid < 25){
            wv0 = g_cw[(2*op)*25 + tid];
            wv1 = g_cw[(2*op+1)*25 + tid];
        }
    };
    pre(0);

    u64 acc2 = 0;
    for (int op = 0; op < 16; ++op){
        __syncthreads();
        s_in2[tid] = pack2(a0, b0);
        if (tid + 256 < 400) s_in2[tid + 256] = pack2(a1, b1);
        if (tid < 25) s_wp[tid] = pack2(wv0, wv1);
        if (op < 15) pre(op + 1);
        __syncthreads();
        #pragma unroll
        for (int u = 0; u < 5; ++u)
            #pragma unroll
            for (int v = 0; v < 5; ++v)
                acc2 = ffma2(s_in2[(ty + 4 - u)*20 + tx + 4 - v], s_wp[u*5 + v], acc2);
    }
    int oy = y0 + ty, ox = x0 + tx;
    if (oy < HP && ox < HP){
        float2 a = unpack2(acc2);
        g_ct[(size_t)n*NPIX + oy*HP + ox] = biasT[0] + a.x + a.y;
    }
}

__global__ void k_nrm(){
    __shared__ float red[256];
    int n = blockIdx.x;
    float s = 0.f;
    for (int p = threadIdx.x; p < NPIX; p += 256){
        float v = g_ct[(size_t)n*NPIX + p];
        s += v*v;
    }
    red[threadIdx.x] = s; __syncthreads();
    for (int o = 128; o; o >>= 1){
        if (threadIdx.x < o) red[threadIdx.x] += red[threadIdx.x + o];
        __syncthreads();
    }
    if (threadIdx.x == 0) g_nrm2[n] = red[0];
}

__global__ void k_scl(const float* __restrict__ ap){
    int n = threadIdx.x;
    if (n < ND){
        float eps = expf(ap[0]) * g_cstdn[n] * sqrtf((float)(NPIX - 1));
        float nr  = sqrtf(g_nrm2[n]);
        g_scl[n] = (nr > eps) ? eps / fmaxf(nr, 1e-12f) : 1.f;
    }
}

__global__ void k_final(const float* __restrict__ mw, float* __restrict__ outp){
    int b = blockIdx.y;
    int p = blockIdx.x*256 + threadIdx.x;
    int y = p >> 8, x = p & 255;
    size_t q = (size_t)(y + 7)*HP + (x + 7);
    float acc = 0.f;
    #pragma unroll
    for (int d = 0; d < 4; ++d){
        int n = b*4 + d;
        float r = g_z[(size_t)n*NPIX + q] - g_ct[(size_t)n*NPIX + q]*g_scl[n];
        r = fminf(fmaxf(r, 0.f), 255.f);
        acc += mw[d]*r;
    }
    outp[(size_t)b*65536 + p] = acc;
}

extern "C" void kernel_launch(void* const* d_in, const int* in_sizes, int n_in,
                              void* d_out, int out_size){
    const float* x      = (const float*)d_in[0];
    const float* bk     = (const float*)d_in[1];
    const float* stdn   = (const float*)d_in[2];
    const float* wienw  = (const float*)d_in[3];
    const float* wiensc = (const float*)d_in[4];
    const float* alpha  = (const float*)d_in[5];
    const float* convw  = (const float*)d_in[6];
    const float* scalef = (const float*)d_in[7];
    const float* biasf  = (const float*)d_in[8];
    const float* biast  = (const float*)d_in[9];
    const float* p1     = (const float*)d_in[10];
    const float* w1     = (const float*)d_in[11];
    const float* s1     = (const float*)d_in[12];
    const float* b1     = (const float*)d_in[13];
    const float* p2     = (const float*)d_in[14];
    const float* w2     = (const float*)d_in[15];
    const float* s2     = (const float*)d_in[16];
    const float* b2     = (const float*)d_in[17];
    const float* aproj  = (const float*)d_in[18];
    const float* mw     = (const float*)d_in[19];
    float* outp = (float*)d_out;

    float *pxp, *pz, *pww, *pcw, *pw1, *pw2, *pf0, *pf1;
    u32 *pw1h, *pw2h;
    float2 *pX, *pT1;
    cudaGetSymbolAddress((void**)&pxp, g_xp);
    cudaGetSymbolAddress((void**)&pz,  g_z);
    cudaGetSymbolAddress((void**)&pww, g_ww);
    cudaGetSymbolAddress((void**)&pcw, g_cw);
    cudaGetSymbolAddress((void**)&pw1, g_w1);
    cudaGetSymbolAddress((void**)&pw2, g_w2);
    cudaGetSymbolAddress((void**)&pw1h, g_w1h);
    cudaGetSymbolAddress((void**)&pw2h, g_w2h);
    cudaGetSymbolAddress((void**)&pf0, g_f0);
    cudaGetSymbolAddress((void**)&pf1, g_f1);
    cudaGetSymbolAddress((void**)&pX,  g_X);
    cudaGetSymbolAddress((void**)&pT1, g_T1);

    const int PB = (NPIX + 255)/256;
    const float INV = 1.0f/(float)HP;
    const int SMEMB = (2*9*64*12 + 8*328)*4;   // 65792 B, same for both layer types

    static bool attr_done = false;
    if (!attr_done){
        cudaFuncSetAttribute(k_mma_conv<32,64>, cudaFuncAttributeMaxDynamicSharedMemorySize, SMEMB);
        cudaFuncSetAttribute(k_mma_conv<64,32>, cudaFuncAttributeMaxDynamicSharedMemorySize, SMEMB);
        attr_done = true;
    }

    k_init_tw<<<1, 288>>>();
    k_pad<<<dim3(PB, NB), 256>>>(x);
    k_alphas<<<1, 288>>>(bk);
    k_psf1<<<(HP*15 + 255)/256, 256>>>(bk);
    k_psf2<<<PB, 256>>>();
    // fft2(xp) -> X
    k_dft_rows_real<<<dim3(HP, NB), 288>>>(pxp, pT1);
    k_dft_line_c<0,0><<<dim3(HP, NB), 288>>>(pT1, pX, 1.f, 1.f, nullptr);
    // edgetaper: ifft2(X*Hf).real blended into xp (fused)
    k_dft_line_c<1,1><<<dim3(HP, NB), 288>>>(pX, pT1, -1.f, INV, nullptr);
    k_dft_cols_real<1><<<dim3(HP, NB), 288>>>(pT1, nullptr, -1.f, INV);

    k_wnorm<<<24, 32>>>(wienw, wiensc, pww, 25);
    k_wnorm<<<32, 32>>>(convw, scalef, pcw, 25);
    k_wnorm<<<320, 32>>>(w1, s1, pw1, 288);
    k_wnorm<<<160, 32>>>(w2, s2, pw2, 576);
    k_wpreph<32,64><<<dim3(54,5), 256>>>(pw1, pw1h);
    k_wpreph<64,32><<<dim3(54,5), 256>>>(pw2, pw2h);
    k_wien1<<<(24*HP*5 + 255)/256, 256>>>();
    k_S<<<PB, 256>>>();

    // Y = fft2(xp) -> X
    k_dft_rows_real<<<dim3(HP, NB), 288>>>(pxp, pT1);
    k_dft_line_c<0,0><<<dim3(HP, NB), 288>>>(pT1, pX, 1.f, 1.f, nullptr);

    k_amp<<<4, 256>>>(alpha);
    k_cstdn<<<1, 32>>>(stdn);

    // z = ifft2(T * Y).real (Wiener product fused)
    k_dft_line_c<1,2><<<dim3(HP, ND), 288>>>(pX, pT1, -1.f, INV, alpha);
    k_dft_cols_real<0><<<dim3(HP, ND), 288>>>(pT1, pz, -1.f, INV);

    // CNN
    k_conv1_mma<<<dim3(9,17,ND), 256>>>(biasf);
    for (int i = 0; i < 5; ++i){
        k_mma_conv<32,64><<<dim3(17,17,ND), 256, SMEMB>>>(
            pf0, pw1h + (size_t)i*2*9*64*12, b1 + i*64, p1 + i*32, nullptr, pf1);
        k_mma_conv<64,32><<<dim3(17,17,ND), 256, SMEMB>>>(
            pf1, pw2h + (size_t)i*4*9*32*12, b2 + i*32, p2 + i*64,
            (i == 0) ? pf0 : nullptr, pf0);
    }
    k_convT<<<dim3(17,17,ND), dim3(16,16)>>>(pf0, biast);

    k_nrm<<<ND, 256>>>();
    k_scl<<<1, 32>>>(aproj);
    k_final<<<dim3(256, NB), 256>>>(mw, outp);
}